// round 1
// baseline (speedup 1.0000x reference)
#include <cuda_runtime.h>
#include <cuda_bf16.h>
#include <math.h>

// Problem constants
#define BB   2
#define TT   2048
#define HH   2048
#define NH   16
#define NKV  8
#define HD   128
#define MM   (BB*TT)            // 4096 rows

// ---------------- scratch (static device globals; no allocation) -------------
__device__ float g_qraw[(size_t)MM * NH * HD];    // [b,t,h,d]
__device__ float g_kraw[(size_t)MM * NKV * HD];
__device__ float g_vraw[(size_t)MM * NKV * HD];
__device__ float g_qt[(size_t)BB * NH * TT * HD]; // [b,h,t,d]
__device__ float g_kt[(size_t)BB * NKV * TT * HD];
__device__ float g_vt[(size_t)BB * NKV * TT * HD];
__device__ float g_ctx[(size_t)MM * NH * HD];     // [b,t,h*HD+d]
__device__ float g_cos[TT * 64];
__device__ float g_sin[TT * 64];

// ---------------- RoPE tables (fp64 for accuracy, stored fp32) ---------------
__global__ void rope_table_kernel() {
    int t = blockIdx.x;
    int j = threadIdx.x;  // 0..63
    double inv = exp(-(double)j * (13.815510557964274 / 64.0)); // theta=1e6
    double ang = (double)t * inv;
    g_cos[t * 64 + j] = (float)cos(ang);
    g_sin[t * 64 + j] = (float)sin(ang);
}

// ---------------- SGEMM: C[M,N] = A[M,K] @ B[K,N], all row-major -------------
// 128x128 tile, BK=8, 256 threads, 8x8 microtile.
__global__ __launch_bounds__(256) void sgemm_kernel(
    const float* __restrict__ A, const float* __restrict__ Bm,
    float* __restrict__ C, int M, int N, int K)
{
    __shared__ float As[8][128];
    __shared__ float Bs[8][128];
    int tid  = threadIdx.x;
    int brow = blockIdx.y, bcol = blockIdx.x;

    int aRow = tid >> 1;             // 0..127
    int aCol = (tid & 1) * 4;        // 0 or 4
    int bRow = tid >> 5;             // 0..7
    int bCol = (tid & 31) * 4;       // 0..124

    const float* Ablk = A + (size_t)brow * 128 * K;
    const float* Bblk = Bm + (size_t)bcol * 128;

    int tr = (tid >> 4) * 8;         // output rows tr..tr+7
    int tc = (tid & 15) * 8;         // output cols tc..tc+7

    float acc[8][8];
    #pragma unroll
    for (int i = 0; i < 8; i++)
        #pragma unroll
        for (int j = 0; j < 8; j++) acc[i][j] = 0.f;

    for (int k0 = 0; k0 < K; k0 += 8) {
        float4 a = *(const float4*)(Ablk + (size_t)aRow * K + k0 + aCol);
        As[aCol + 0][aRow] = a.x;
        As[aCol + 1][aRow] = a.y;
        As[aCol + 2][aRow] = a.z;
        As[aCol + 3][aRow] = a.w;
        float4 b = *(const float4*)(Bblk + (size_t)(k0 + bRow) * N + bCol);
        *(float4*)&Bs[bRow][bCol] = b;
        __syncthreads();
        #pragma unroll
        for (int k = 0; k < 8; k++) {
            float ra[8], rb[8];
            *(float4*)&ra[0] = *(float4*)&As[k][tr];
            *(float4*)&ra[4] = *(float4*)&As[k][tr + 4];
            *(float4*)&rb[0] = *(float4*)&Bs[k][tc];
            *(float4*)&rb[4] = *(float4*)&Bs[k][tc + 4];
            #pragma unroll
            for (int i = 0; i < 8; i++)
                #pragma unroll
                for (int j = 0; j < 8; j++)
                    acc[i][j] += ra[i] * rb[j];
        }
        __syncthreads();
    }
    float* Crow = C + (size_t)(brow * 128 + tr) * N + bcol * 128 + tc;
    #pragma unroll
    for (int i = 0; i < 8; i++) {
        *(float4*)(Crow + (size_t)i * N)     = *(float4*)&acc[i][0];
        *(float4*)(Crow + (size_t)i * N + 4) = *(float4*)&acc[i][4];
    }
}

// ------------- RMSNorm + RoPE + transpose [b,t,h,d] -> [b,h,t,d] -------------
__global__ __launch_bounds__(128) void norm_rope_kernel(
    const float* __restrict__ src, float* __restrict__ dst,
    const float* __restrict__ w, int nheads)
{
    int r = blockIdx.x;              // (b*T+t)*nheads + h
    int d = threadIdx.x;             // 0..127
    int h  = r % nheads;
    int bt = r / nheads;
    int t  = bt % TT;
    int b  = bt / TT;

    float val = src[(size_t)r * HD + d];
    __shared__ float red[4];
    __shared__ float sh[HD];

    float ss = val * val;
    #pragma unroll
    for (int off = 16; off; off >>= 1)
        ss += __shfl_xor_sync(0xffffffffu, ss, off);
    if ((d & 31) == 0) red[d >> 5] = ss;
    __syncthreads();
    float tot = red[0] + red[1] + red[2] + red[3];
    float nv = val * rsqrtf(tot * (1.0f / HD) + 1e-6f) * w[d];
    sh[d] = nv;
    __syncthreads();

    int j = d & 63;
    float c = g_cos[t * 64 + j];
    float s = g_sin[t * 64 + j];
    float other = (d < 64) ? -sh[d + 64] : sh[d - 64];
    float out = nv * c + other * s;

    dst[((size_t)(b * nheads + h) * TT + t) * HD + d] = out;
}

// ------------- V transpose [b,t,h,d] -> [b,h,t,d] ----------------------------
__global__ __launch_bounds__(128) void transpose_kernel(
    const float* __restrict__ src, float* __restrict__ dst, int nheads)
{
    int r = blockIdx.x;
    int d = threadIdx.x;
    int h  = r % nheads;
    int bt = r / nheads;
    int t  = bt % TT;
    int b  = bt / TT;
    dst[((size_t)(b * nheads + h) * TT + t) * HD + d] = src[(size_t)r * HD + d];
}

// ------------- Causal flash attention ----------------------------------------
// grid (T/64, B*NH), 256 threads. BQ=BK=64, D=128.
#define FQ_STRIDE 65     // QsT/KsT row stride (transposed [d][row])
#define FV_STRIDE 132    // Vs row stride
#define FP_STRIDE 68     // Ps row stride
#define FLASH_SMEM ((2 * 128 * FQ_STRIDE + 64 * FV_STRIDE + 64 * FP_STRIDE) * 4)

__global__ __launch_bounds__(256) void flash_kernel(
    const float* __restrict__ Q, const float* __restrict__ Kt,
    const float* __restrict__ Vt, float* __restrict__ ctx)
{
    extern __shared__ float sm[];
    float* QsT = sm;                          // [128][65]
    float* KsT = QsT + 128 * FQ_STRIDE;       // [128][65]
    float* Vs  = KsT + 128 * FQ_STRIDE;       // [64][132]
    float* Ps  = Vs  + 64 * FV_STRIDE;        // [64][68]

    int tid = threadIdx.x;
    int qb  = blockIdx.x;                     // 0..31
    int bh  = blockIdx.y;                     // 0..31
    int b = bh / NH, h = bh % NH;
    int kvh = h / (NH / NKV);

    const float* Qbase = Q  + ((size_t)(b * NH  + h)   * TT + qb * 64) * HD;
    const float* Kbase = Kt + ((size_t)(b * NKV + kvh) * TT) * HD;
    const float* Vbase = Vt + ((size_t)(b * NKV + kvh) * TT) * HD;

    // load Q tile (transposed into smem)
    #pragma unroll
    for (int it = 0; it < 8; ++it) {
        int flat = it * 256 + tid;
        int row  = flat >> 5;
        int d0   = (flat & 31) * 4;
        float4 v = *(const float4*)(Qbase + (size_t)row * HD + d0);
        QsT[(d0 + 0) * FQ_STRIDE + row] = v.x;
        QsT[(d0 + 1) * FQ_STRIDE + row] = v.y;
        QsT[(d0 + 2) * FQ_STRIDE + row] = v.z;
        QsT[(d0 + 3) * FQ_STRIDE + row] = v.w;
    }

    int tg = tid >> 4;   // row group: rows tg*4..+3
    int tc = tid & 15;   // S cols tc*4..+3 ; O cols tc*8..+7

    float o[4][8];
    #pragma unroll
    for (int i = 0; i < 4; i++)
        #pragma unroll
        for (int j = 0; j < 8; j++) o[i][j] = 0.f;
    float m[4] = {-1e30f, -1e30f, -1e30f, -1e30f};
    float l[4] = {0.f, 0.f, 0.f, 0.f};

    const float scale = 0.08838834764831845f;   // 128^-0.5
    const float L2E = 1.44269504088896f;

    int nkb = qb + 1;
    for (int kb = 0; kb < nkb; ++kb) {
        const float* Kp = Kbase + (size_t)kb * 64 * HD;
        const float* Vp = Vbase + (size_t)kb * 64 * HD;
        __syncthreads();
        #pragma unroll
        for (int it = 0; it < 8; ++it) {
            int flat = it * 256 + tid;
            int row  = flat >> 5;
            int d0   = (flat & 31) * 4;
            float4 kv = *(const float4*)(Kp + (size_t)row * HD + d0);
            KsT[(d0 + 0) * FQ_STRIDE + row] = kv.x;
            KsT[(d0 + 1) * FQ_STRIDE + row] = kv.y;
            KsT[(d0 + 2) * FQ_STRIDE + row] = kv.z;
            KsT[(d0 + 3) * FQ_STRIDE + row] = kv.w;
            float4 vv = *(const float4*)(Vp + (size_t)row * HD + d0);
            *(float4*)&Vs[row * FV_STRIDE + d0] = vv;
        }
        __syncthreads();

        float s[4][4];
        #pragma unroll
        for (int i = 0; i < 4; i++)
            #pragma unroll
            for (int j = 0; j < 4; j++) s[i][j] = 0.f;

        #pragma unroll 8
        for (int d = 0; d < 128; ++d) {
            float ra[4], rb[4];
            #pragma unroll
            for (int i = 0; i < 4; i++) ra[i] = QsT[d * FQ_STRIDE + tg * 4 + i];
            #pragma unroll
            for (int j = 0; j < 4; j++) rb[j] = KsT[d * FQ_STRIDE + tc * 4 + j];
            #pragma unroll
            for (int i = 0; i < 4; i++)
                #pragma unroll
                for (int j = 0; j < 4; j++)
                    s[i][j] += ra[i] * rb[j];
        }

        bool diag = (kb == qb);
        #pragma unroll
        for (int i = 0; i < 4; i++) {
            int qg = qb * 64 + tg * 4 + i;
            float rm = -1e30f;
            #pragma unroll
            for (int j = 0; j < 4; j++) {
                float sv = s[i][j] * scale;
                if (diag) {
                    int kg = kb * 64 + tc * 4 + j;
                    if (kg > qg) sv = -1e30f;
                }
                s[i][j] = sv;
                rm = fmaxf(rm, sv);
            }
            #pragma unroll
            for (int off = 1; off < 16; off <<= 1)
                rm = fmaxf(rm, __shfl_xor_sync(0xffffffffu, rm, off));
            float mnew  = fmaxf(m[i], rm);
            float alpha = exp2f((m[i] - mnew) * L2E);
            m[i] = mnew;
            float rs = 0.f;
            #pragma unroll
            for (int j = 0; j < 4; j++) {
                float p = exp2f((s[i][j] - mnew) * L2E);
                s[i][j] = p;
                rs += p;
            }
            #pragma unroll
            for (int off = 1; off < 16; off <<= 1)
                rs += __shfl_xor_sync(0xffffffffu, rs, off);
            l[i] = l[i] * alpha + rs;
            #pragma unroll
            for (int jd = 0; jd < 8; jd++) o[i][jd] *= alpha;
            #pragma unroll
            for (int j = 0; j < 4; j++)
                Ps[(tg * 4 + i) * FP_STRIDE + tc * 4 + j] = s[i][j];
        }
        __syncthreads();

        // O += P @ V
        #pragma unroll 4
        for (int kk = 0; kk < 64; ++kk) {
            float pv[4];
            #pragma unroll
            for (int i = 0; i < 4; i++) pv[i] = Ps[(tg * 4 + i) * FP_STRIDE + kk];
            float4 v0 = *(float4*)&Vs[kk * FV_STRIDE + tc * 8];
            float4 v1 = *(float4*)&Vs[kk * FV_STRIDE + tc * 8 + 4];
            #pragma unroll
            for (int i = 0; i < 4; i++) {
                o[i][0] += pv[i] * v0.x;  o[i][1] += pv[i] * v0.y;
                o[i][2] += pv[i] * v0.z;  o[i][3] += pv[i] * v0.w;
                o[i][4] += pv[i] * v1.x;  o[i][5] += pv[i] * v1.y;
                o[i][6] += pv[i] * v1.z;  o[i][7] += pv[i] * v1.w;
            }
        }
    }

    // epilogue: ctx[b, t, h*HD + d]
    #pragma unroll
    for (int i = 0; i < 4; i++) {
        int q = qb * 64 + tg * 4 + i;
        float inv_l = 1.0f / l[i];
        float4 r0, r1;
        r0.x = o[i][0] * inv_l; r0.y = o[i][1] * inv_l;
        r0.z = o[i][2] * inv_l; r0.w = o[i][3] * inv_l;
        r1.x = o[i][4] * inv_l; r1.y = o[i][5] * inv_l;
        r1.z = o[i][6] * inv_l; r1.w = o[i][7] * inv_l;
        float* cp = ctx + (size_t)(b * TT + q) * (NH * HD) + h * HD + tc * 8;
        *(float4*)(cp)     = r0;
        *(float4*)(cp + 4) = r1;
    }
}

// ---------------------------- launch -----------------------------------------
extern "C" void kernel_launch(void* const* d_in, const int* in_sizes, int n_in,
                              void* d_out, int out_size)
{
    const float* x    = (const float*)d_in[0];
    // d_in[1] = attn_mask (pure causal; applied analytically)
    const float* Wq   = (const float*)d_in[2];
    const float* Wk   = (const float*)d_in[3];
    const float* Wv   = (const float*)d_in[4];
    const float* Wo   = (const float*)d_in[5];
    const float* qnw  = (const float*)d_in[6];
    const float* knw  = (const float*)d_in[7];
    float* out = (float*)d_out;

    float *qraw, *kraw, *vraw, *qt, *kt, *vt, *ctx;
    cudaGetSymbolAddress((void**)&qraw, g_qraw);
    cudaGetSymbolAddress((void**)&kraw, g_kraw);
    cudaGetSymbolAddress((void**)&vraw, g_vraw);
    cudaGetSymbolAddress((void**)&qt,   g_qt);
    cudaGetSymbolAddress((void**)&kt,   g_kt);
    cudaGetSymbolAddress((void**)&vt,   g_vt);
    cudaGetSymbolAddress((void**)&ctx,  g_ctx);

    // QKV projections
    sgemm_kernel<<<dim3(NH  * HD / 128, MM / 128), 256>>>(x, Wq, qraw, MM, NH  * HD, HH);
    sgemm_kernel<<<dim3(NKV * HD / 128, MM / 128), 256>>>(x, Wk, kraw, MM, NKV * HD, HH);
    sgemm_kernel<<<dim3(NKV * HD / 128, MM / 128), 256>>>(x, Wv, vraw, MM, NKV * HD, HH);

    // RoPE tables + RMSNorm/RoPE/transpose
    rope_table_kernel<<<TT, 64>>>();
    norm_rope_kernel<<<BB * TT * NH, 128>>>(qraw, qt, qnw, NH);
    norm_rope_kernel<<<BB * TT * NKV, 128>>>(kraw, kt, knw, NKV);
    transpose_kernel<<<BB * TT * NKV, 128>>>(vraw, vt, NKV);

    // Flash attention
    cudaFuncSetAttribute(flash_kernel, cudaFuncAttributeMaxDynamicSharedMemorySize,
                         FLASH_SMEM);
    flash_kernel<<<dim3(TT / 64, BB * NH), 256, FLASH_SMEM>>>(qt, kt, vt, ctx);

    // Output projection
    sgemm_kernel<<<dim3(HH / 128, MM / 128), 256>>>(ctx, Wo, out, MM, HH, HH);
}

// round 3
// speedup vs baseline: 3.1268x; 3.1268x over previous
#include <cuda_runtime.h>
#include <cuda_bf16.h>
#include <cstdint>
#include <cstddef>
#include <math.h>

// Problem constants
#define BB   2
#define TT   2048
#define HH   2048
#define NH   16
#define NKV  8
#define HD   128
#define MM   (BB*TT)            // 4096 rows

// ---------------- scratch (static device globals; no allocation) -------------
__device__ float g_qraw[(size_t)MM * NH * HD];    // [b,t,h,d]
__device__ float g_kraw[(size_t)MM * NKV * HD];
__device__ float g_vraw[(size_t)MM * NKV * HD];
__device__ float g_qt[(size_t)BB * NH * TT * HD]; // [b,h,t,d]  (tf32-rounded)
__device__ float g_kt[(size_t)BB * NKV * TT * HD];
__device__ float g_vt[(size_t)BB * NKV * TT * HD];
__device__ float g_ctx[(size_t)MM * NH * HD];     // [b,t,h*HD+d]
__device__ float g_cos[TT * 64];
__device__ float g_sin[TT * 64];

// ---------------- helpers ----------------------------------------------------
__device__ __forceinline__ float to_tf32(float x) {
    uint32_t u;
    asm("cvt.rna.tf32.f32 %0, %1;" : "=r"(u) : "f"(x));
    return __uint_as_float(u);
}

__device__ __forceinline__ void mma_tf32(float c[4], const uint32_t a[4],
                                         const uint32_t b[2]) {
    asm volatile(
        "mma.sync.aligned.m16n8k8.row.col.f32.tf32.tf32.f32 "
        "{%0,%1,%2,%3}, {%4,%5,%6,%7}, {%8,%9}, {%0,%1,%2,%3};\n"
        : "+f"(c[0]), "+f"(c[1]), "+f"(c[2]), "+f"(c[3])
        : "r"(a[0]), "r"(a[1]), "r"(a[2]), "r"(a[3]), "r"(b[0]), "r"(b[1]));
}

// ---------------- RoPE tables (fp64 for accuracy, stored fp32) ---------------
__global__ void rope_table_kernel() {
    int t = blockIdx.x;
    int j = threadIdx.x;  // 0..63
    double inv = exp(-(double)j * (13.815510557964274 / 64.0)); // theta=1e6
    double ang = (double)t * inv;
    g_cos[t * 64 + j] = (float)cos(ang);
    g_sin[t * 64 + j] = (float)sin(ang);
}

// ---------------- GEMM tf32 tensor-core: C = A[M,K] @ B[K,N], row-major ------
// 128x128 tile, BK=16, 256 threads, 8 warps each 32x64.
#define GS 136   // smem row stride (floats): conflict-free fragment gathers
__global__ __launch_bounds__(256, 2) void gemm_tf32_kernel(
    const float* __restrict__ A, const float* __restrict__ Bm,
    float* __restrict__ C, int M, int N, int K)
{
    __shared__ float As[16 * GS];   // [k][m]
    __shared__ float Bs[16 * GS];   // [k][n]

    int tid = threadIdx.x;
    int wid = tid >> 5, lane = tid & 31;
    int g = lane >> 2, tg = lane & 3;
    int warpRow = wid >> 1, warpCol = wid & 1;  // 4 x 2 warps
    int brow = blockIdx.y * 128, bcol = blockIdx.x * 128;

    // global-load mapping
    int aRow[2], aC4[2], bRow[2], bC4[2];
    #pragma unroll
    for (int it = 0; it < 2; ++it) {
        int idx = it * 256 + tid;
        aRow[it] = idx >> 2;        aC4[it] = (idx & 3) * 4;
        bRow[it] = idx >> 5;        bC4[it] = (idx & 31) * 4;
    }

    float acc[2][8][4];
    #pragma unroll
    for (int mi = 0; mi < 2; mi++)
        #pragma unroll
        for (int ni = 0; ni < 8; ni++)
            #pragma unroll
            for (int c = 0; c < 4; c++) acc[mi][ni][c] = 0.f;

    float4 pa[2], pb[2];
    #pragma unroll
    for (int it = 0; it < 2; ++it) {
        pa[it] = *(const float4*)(A + (size_t)(brow + aRow[it]) * K + aC4[it]);
        pb[it] = *(const float4*)(Bm + (size_t)bRow[it] * N + bcol + bC4[it]);
    }

    for (int k0 = 0; k0 < K; k0 += 16) {
        // store staged tiles (convert to tf32)
        #pragma unroll
        for (int it = 0; it < 2; ++it) {
            As[(aC4[it] + 0) * GS + aRow[it]] = to_tf32(pa[it].x);
            As[(aC4[it] + 1) * GS + aRow[it]] = to_tf32(pa[it].y);
            As[(aC4[it] + 2) * GS + aRow[it]] = to_tf32(pa[it].z);
            As[(aC4[it] + 3) * GS + aRow[it]] = to_tf32(pa[it].w);
            Bs[bRow[it] * GS + bC4[it] + 0] = to_tf32(pb[it].x);
            Bs[bRow[it] * GS + bC4[it] + 1] = to_tf32(pb[it].y);
            Bs[bRow[it] * GS + bC4[it] + 2] = to_tf32(pb[it].z);
            Bs[bRow[it] * GS + bC4[it] + 3] = to_tf32(pb[it].w);
        }
        __syncthreads();

        if (k0 + 16 < K) {
            #pragma unroll
            for (int it = 0; it < 2; ++it) {
                pa[it] = *(const float4*)(A + (size_t)(brow + aRow[it]) * K + k0 + 16 + aC4[it]);
                pb[it] = *(const float4*)(Bm + (size_t)(k0 + 16 + bRow[it]) * N + bcol + bC4[it]);
            }
        }

        #pragma unroll
        for (int ks = 0; ks < 2; ++ks) {
            int kk = ks * 8;
            uint32_t af[2][4];
            #pragma unroll
            for (int mi = 0; mi < 2; mi++) {
                int r = warpRow * 32 + mi * 16 + g;
                af[mi][0] = __float_as_uint(As[(kk + tg) * GS + r]);
                af[mi][1] = __float_as_uint(As[(kk + tg) * GS + r + 8]);
                af[mi][2] = __float_as_uint(As[(kk + tg + 4) * GS + r]);
                af[mi][3] = __float_as_uint(As[(kk + tg + 4) * GS + r + 8]);
            }
            uint32_t bf[8][2];
            #pragma unroll
            for (int ni = 0; ni < 8; ni++) {
                int cn = warpCol * 64 + ni * 8 + g;
                bf[ni][0] = __float_as_uint(Bs[(kk + tg) * GS + cn]);
                bf[ni][1] = __float_as_uint(Bs[(kk + tg + 4) * GS + cn]);
            }
            #pragma unroll
            for (int mi = 0; mi < 2; mi++)
                #pragma unroll
                for (int ni = 0; ni < 8; ni++)
                    mma_tf32(acc[mi][ni], af[mi], bf[ni]);
        }
        __syncthreads();
    }

    // epilogue
    #pragma unroll
    for (int mi = 0; mi < 2; mi++) {
        int r0 = brow + warpRow * 32 + mi * 16 + g;
        #pragma unroll
        for (int ni = 0; ni < 8; ni++) {
            int cn = bcol + warpCol * 64 + ni * 8 + tg * 2;
            *(float2*)(C + (size_t)r0 * N + cn) = make_float2(acc[mi][ni][0], acc[mi][ni][1]);
            *(float2*)(C + (size_t)(r0 + 8) * N + cn) = make_float2(acc[mi][ni][2], acc[mi][ni][3]);
        }
    }
}

// ------------- RMSNorm + RoPE + transpose [b,t,h,d] -> [b,h,t,d] -------------
__global__ __launch_bounds__(128) void norm_rope_kernel(
    const float* __restrict__ src, float* __restrict__ dst,
    const float* __restrict__ w, int nheads)
{
    int r = blockIdx.x;              // (b*T+t)*nheads + h
    int d = threadIdx.x;             // 0..127
    int h  = r % nheads;
    int bt = r / nheads;
    int t  = bt % TT;
    int b  = bt / TT;

    float val = src[(size_t)r * HD + d];
    __shared__ float red[4];
    __shared__ float sh[HD];

    float ss = val * val;
    #pragma unroll
    for (int off = 16; off; off >>= 1)
        ss += __shfl_xor_sync(0xffffffffu, ss, off);
    if ((d & 31) == 0) red[d >> 5] = ss;
    __syncthreads();
    float tot = red[0] + red[1] + red[2] + red[3];
    float nv = val * rsqrtf(tot * (1.0f / HD) + 1e-6f) * w[d];
    sh[d] = nv;
    __syncthreads();

    int j = d & 63;
    float c = g_cos[t * 64 + j];
    float s = g_sin[t * 64 + j];
    float other = (d < 64) ? -sh[d + 64] : sh[d - 64];
    float out = nv * c + other * s;

    dst[((size_t)(b * nheads + h) * TT + t) * HD + d] = to_tf32(out);
}

// ------------- V transpose [b,t,h,d] -> [b,h,t,d] (tf32 round) ---------------
__global__ __launch_bounds__(128) void transpose_kernel(
    const float* __restrict__ src, float* __restrict__ dst, int nheads)
{
    int r = blockIdx.x;
    int d = threadIdx.x;
    int h  = r % nheads;
    int bt = r / nheads;
    int t  = bt % TT;
    int b  = bt / TT;
    dst[((size_t)(b * nheads + h) * TT + t) * HD + d] = to_tf32(src[(size_t)r * HD + d]);
}

// ------------- Causal flash attention, tf32 tensor cores ---------------------
// grid (T/64, B*NH), 128 threads (4 warps). BQ=64, key tile 64, D=128.
// warp w owns Q rows [w*16, w*16+16).
#define KS_STR 132     // Ks row stride
#define VS_STR 136     // Vs row stride
#define QS_STR 132     // Q stage stride
#define PS_STR 68      // Ps stride
#define FL_KS_FLOATS (64 * KS_STR)
#define FL_VS_FLOATS (64 * VS_STR)
#define FL_U_FLOATS  (64 * QS_STR)   // union(Qstage, Ps): Qstage bigger
#define FLASH_SMEM ((FL_KS_FLOATS + FL_VS_FLOATS + FL_U_FLOATS) * 4)

__global__ __launch_bounds__(128) void flash_tf32_kernel(
    const float* __restrict__ Q, const float* __restrict__ Kt,
    const float* __restrict__ Vt, float* __restrict__ ctx)
{
    extern __shared__ float sm[];
    float* Ks = sm;
    float* Vs = Ks + FL_KS_FLOATS;
    float* Us = Vs + FL_VS_FLOATS;   // Q stage, later Ps
    float* Ps = Us;

    int tid = threadIdx.x;
    int wid = tid >> 5, lane = tid & 31;
    int g = lane >> 2, tg = lane & 3;

    int qb = blockIdx.x;            // 0..31
    int bh = blockIdx.y;            // 0..31
    int b = bh / NH, h = bh % NH;
    int kvh = h / (NH / NKV);

    const float* Qbase = Q  + ((size_t)(b * NH  + h)   * TT + qb * 64) * HD;
    const float* Kbase = Kt + ((size_t)(b * NKV + kvh) * TT) * HD;
    const float* Vbase = Vt + ((size_t)(b * NKV + kvh) * TT) * HD;

    // ---- stage Q into smem, then load fragments into registers -------------
    #pragma unroll
    for (int it = 0; it < 16; ++it) {
        int idx = it * 128 + tid;
        int row = idx >> 5;
        int c4  = (idx & 31) * 4;
        float4 v = *(const float4*)(Qbase + (size_t)row * HD + c4);
        Us[row * QS_STR + c4 + 0] = v.x;
        Us[row * QS_STR + c4 + 1] = v.y;
        Us[row * QS_STR + c4 + 2] = v.z;
        Us[row * QS_STR + c4 + 3] = v.w;
    }
    __syncthreads();

    uint32_t qa[16][4];
    {
        int r = wid * 16 + g;
        #pragma unroll
        for (int ks = 0; ks < 16; ++ks) {
            int kk = ks * 8;
            qa[ks][0] = __float_as_uint(Us[r * QS_STR + kk + tg]);
            qa[ks][1] = __float_as_uint(Us[(r + 8) * QS_STR + kk + tg]);
            qa[ks][2] = __float_as_uint(Us[r * QS_STR + kk + tg + 4]);
            qa[ks][3] = __float_as_uint(Us[(r + 8) * QS_STR + kk + tg + 4]);
        }
    }

    float o[16][4];
    #pragma unroll
    for (int ni = 0; ni < 16; ni++)
        #pragma unroll
        for (int c = 0; c < 4; c++) o[ni][c] = 0.f;
    float mrow[2] = {-1e30f, -1e30f};
    float lrow[2] = {0.f, 0.f};

    const float scale = 0.08838834764831845f;   // 128^-0.5
    const float L2E = 1.44269504088896f;

    for (int kb = 0; kb <= qb; ++kb) {
        const float* Kp = Kbase + (size_t)kb * 64 * HD;
        const float* Vp = Vbase + (size_t)kb * 64 * HD;
        __syncthreads();   // prior iteration's PV reads of Ks/Vs/Ps complete
        #pragma unroll
        for (int it = 0; it < 16; ++it) {
            int idx = it * 128 + tid;
            int row = idx >> 5;
            int c4  = (idx & 31) * 4;
            float4 kv = *(const float4*)(Kp + (size_t)row * HD + c4);
            Ks[row * KS_STR + c4 + 0] = kv.x;
            Ks[row * KS_STR + c4 + 1] = kv.y;
            Ks[row * KS_STR + c4 + 2] = kv.z;
            Ks[row * KS_STR + c4 + 3] = kv.w;
            float4 vv = *(const float4*)(Vp + (size_t)row * HD + c4);
            Vs[row * VS_STR + c4 + 0] = vv.x;
            Vs[row * VS_STR + c4 + 1] = vv.y;
            Vs[row * VS_STR + c4 + 2] = vv.z;
            Vs[row * VS_STR + c4 + 3] = vv.w;
        }
        __syncthreads();

        // ---- S = Q @ K^T (16 rows x 64 keys per warp) -----------------------
        float s[8][4];
        #pragma unroll
        for (int ni = 0; ni < 8; ni++)
            #pragma unroll
            for (int c = 0; c < 4; c++) s[ni][c] = 0.f;

        #pragma unroll
        for (int ks = 0; ks < 16; ++ks) {
            int kk = ks * 8;
            uint32_t bf[8][2];
            #pragma unroll
            for (int ni = 0; ni < 8; ni++) {
                int key = ni * 8 + g;
                bf[ni][0] = __float_as_uint(Ks[key * KS_STR + kk + tg]);
                bf[ni][1] = __float_as_uint(Ks[key * KS_STR + kk + tg + 4]);
            }
            #pragma unroll
            for (int ni = 0; ni < 8; ni++)
                mma_tf32(s[ni], qa[ks], bf[ni]);
        }

        // ---- online softmax -------------------------------------------------
        bool diag = (kb == qb);
        int rowA = wid * 16 + g;       // local q row (c0,c1)
        int rowB = rowA + 8;           // (c2,c3)
        float mA = -1e30f, mB = -1e30f;
        #pragma unroll
        for (int ni = 0; ni < 8; ni++) {
            #pragma unroll
            for (int c = 0; c < 4; c++) {
                float sv = s[ni][c] * scale;
                if (diag) {
                    int kcol = ni * 8 + tg * 2 + (c & 1);
                    int qrow = (c < 2) ? rowA : rowB;
                    if (kcol > qrow) sv = -1e30f;
                }
                s[ni][c] = sv;
            }
            mA = fmaxf(mA, fmaxf(s[ni][0], s[ni][1]));
            mB = fmaxf(mB, fmaxf(s[ni][2], s[ni][3]));
        }
        #pragma unroll
        for (int off = 1; off < 4; off <<= 1) {
            mA = fmaxf(mA, __shfl_xor_sync(0xffffffffu, mA, off));
            mB = fmaxf(mB, __shfl_xor_sync(0xffffffffu, mB, off));
        }
        float mnA = fmaxf(mrow[0], mA);
        float mnB = fmaxf(mrow[1], mB);
        float alA = exp2f((mrow[0] - mnA) * L2E);
        float alB = exp2f((mrow[1] - mnB) * L2E);
        mrow[0] = mnA; mrow[1] = mnB;

        float lA = 0.f, lB = 0.f;
        #pragma unroll
        for (int ni = 0; ni < 8; ni++) {
            s[ni][0] = exp2f((s[ni][0] - mnA) * L2E);
            s[ni][1] = exp2f((s[ni][1] - mnA) * L2E);
            s[ni][2] = exp2f((s[ni][2] - mnB) * L2E);
            s[ni][3] = exp2f((s[ni][3] - mnB) * L2E);
            lA += s[ni][0] + s[ni][1];
            lB += s[ni][2] + s[ni][3];
        }
        #pragma unroll
        for (int off = 1; off < 4; off <<= 1) {
            lA += __shfl_xor_sync(0xffffffffu, lA, off);
            lB += __shfl_xor_sync(0xffffffffu, lB, off);
        }
        lrow[0] = lrow[0] * alA + lA;
        lrow[1] = lrow[1] * alB + lB;
        #pragma unroll
        for (int ni = 0; ni < 16; ni++) {
            o[ni][0] *= alA; o[ni][1] *= alA;
            o[ni][2] *= alB; o[ni][3] *= alB;
        }

        // write P (tf32) to smem for the PV mma
        #pragma unroll
        for (int ni = 0; ni < 8; ni++) {
            int cn = ni * 8 + tg * 2;
            Ps[rowA * PS_STR + cn]     = to_tf32(s[ni][0]);
            Ps[rowA * PS_STR + cn + 1] = to_tf32(s[ni][1]);
            Ps[rowB * PS_STR + cn]     = to_tf32(s[ni][2]);
            Ps[rowB * PS_STR + cn + 1] = to_tf32(s[ni][3]);
        }
        __syncthreads();

        // ---- O += P @ V -----------------------------------------------------
        #pragma unroll
        for (int ks = 0; ks < 8; ++ks) {
            int kk = ks * 8;
            uint32_t pa[4];
            int r = wid * 16 + g;
            pa[0] = __float_as_uint(Ps[r * PS_STR + kk + tg]);
            pa[1] = __float_as_uint(Ps[(r + 8) * PS_STR + kk + tg]);
            pa[2] = __float_as_uint(Ps[r * PS_STR + kk + tg + 4]);
            pa[3] = __float_as_uint(Ps[(r + 8) * PS_STR + kk + tg + 4]);
            #pragma unroll
            for (int ni = 0; ni < 16; ni++) {
                uint32_t bf[2];
                int dn = ni * 8 + g;
                bf[0] = __float_as_uint(Vs[(kk + tg) * VS_STR + dn]);
                bf[1] = __float_as_uint(Vs[(kk + tg + 4) * VS_STR + dn]);
                mma_tf32(o[ni], pa, bf);
            }
        }
    }

    // ---- epilogue: ctx[b, t, h*HD + d] --------------------------------------
    float ivA = 1.0f / lrow[0];
    float ivB = 1.0f / lrow[1];
    int qA = qb * 64 + wid * 16 + g;
    int qB = qA + 8;
    float* cpA = ctx + (size_t)(b * TT + qA) * (NH * HD) + h * HD;
    float* cpB = ctx + (size_t)(b * TT + qB) * (NH * HD) + h * HD;
    #pragma unroll
    for (int ni = 0; ni < 16; ni++) {
        int dn = ni * 8 + tg * 2;
        *(float2*)(cpA + dn) = make_float2(o[ni][0] * ivA, o[ni][1] * ivA);
        *(float2*)(cpB + dn) = make_float2(o[ni][2] * ivB, o[ni][3] * ivB);
    }
}

// ---------------------------- launch -----------------------------------------
extern "C" void kernel_launch(void* const* d_in, const int* in_sizes, int n_in,
                              void* d_out, int out_size)
{
    const float* x    = (const float*)d_in[0];
    // d_in[1] = attn_mask (pure causal; applied analytically)
    const float* Wq   = (const float*)d_in[2];
    const float* Wk   = (const float*)d_in[3];
    const float* Wv   = (const float*)d_in[4];
    const float* Wo   = (const float*)d_in[5];
    const float* qnw  = (const float*)d_in[6];
    const float* knw  = (const float*)d_in[7];
    float* out = (float*)d_out;

    float *qraw, *kraw, *vraw, *qt, *kt, *vt, *ctx;
    cudaGetSymbolAddress((void**)&qraw, g_qraw);
    cudaGetSymbolAddress((void**)&kraw, g_kraw);
    cudaGetSymbolAddress((void**)&vraw, g_vraw);
    cudaGetSymbolAddress((void**)&qt,   g_qt);
    cudaGetSymbolAddress((void**)&kt,   g_kt);
    cudaGetSymbolAddress((void**)&vt,   g_vt);
    cudaGetSymbolAddress((void**)&ctx,  g_ctx);

    // QKV projections (tf32 tensor cores)
    gemm_tf32_kernel<<<dim3(NH  * HD / 128, MM / 128), 256>>>(x, Wq, qraw, MM, NH  * HD, HH);
    gemm_tf32_kernel<<<dim3(NKV * HD / 128, MM / 128), 256>>>(x, Wk, kraw, MM, NKV * HD, HH);
    gemm_tf32_kernel<<<dim3(NKV * HD / 128, MM / 128), 256>>>(x, Wv, vraw, MM, NKV * HD, HH);

    // RoPE tables + RMSNorm/RoPE/transpose (outputs tf32-rounded)
    rope_table_kernel<<<TT, 64>>>();
    norm_rope_kernel<<<BB * TT * NH, 128>>>(qraw, qt, qnw, NH);
    norm_rope_kernel<<<BB * TT * NKV, 128>>>(kraw, kt, knw, NKV);
    transpose_kernel<<<BB * TT * NKV, 128>>>(vraw, vt, NKV);

    // Flash attention (tf32 tensor cores)
    cudaFuncSetAttribute(flash_tf32_kernel, cudaFuncAttributeMaxDynamicSharedMemorySize,
                         FLASH_SMEM);
    flash_tf32_kernel<<<dim3(TT / 64, BB * NH), 128, FLASH_SMEM>>>(qt, kt, vt, ctx);

    // Output projection
    gemm_tf32_kernel<<<dim3(HH / 128, MM / 128), 256>>>(ctx, Wo, out, MM, HH, HH);
}

// round 5
// speedup vs baseline: 4.7557x; 1.5209x over previous
#include <cuda_runtime.h>
#include <cuda_fp16.h>
#include <cuda_bf16.h>
#include <cstdint>
#include <cstddef>
#include <math.h>

// Problem constants
#define BB   2
#define TT   2048
#define HH   2048
#define NH   16
#define NKV  8
#define HD   128
#define MM   (BB*TT)            // 4096 rows

// ---------------- scratch (static device globals; no allocation) -------------
__device__ float g_qraw[(size_t)MM * NH * HD];    // [b,t,h,d] fp32
__device__ float g_kraw[(size_t)MM * NKV * HD];
__device__ float g_vraw[(size_t)MM * NKV * HD];
__device__ __half g_qt[(size_t)BB * NH * TT * HD]; // [b,h,t,d] fp16
__device__ __half g_kt[(size_t)BB * NKV * TT * HD];
__device__ __half g_vt[(size_t)BB * NKV * TT * HD];
__device__ __half g_xh[(size_t)MM * HH];           // x fp16
__device__ __half g_wq[(size_t)2048 * 2048];       // W^T [N,K] fp16
__device__ __half g_wk[(size_t)1024 * 2048];
__device__ __half g_wv[(size_t)1024 * 2048];
__device__ __half g_wo[(size_t)2048 * 2048];
__device__ __half g_ctx[(size_t)MM * HH];          // [b*T+t, h*HD+d] fp16
__device__ float g_cos[TT * 64];
__device__ float g_sin[TT * 64];

// ---------------- helpers ----------------------------------------------------
__device__ __forceinline__ uint32_t smem_u32(const void* p) {
    uint32_t a;
    asm("{ .reg .u64 t; cvta.to.shared.u64 t, %1; cvt.u32.u64 %0, t; }" : "=r"(a) : "l"(p));
    return a;
}

__device__ __forceinline__ void mma_f16(float c[4], const uint32_t a[4],
                                        uint32_t b0, uint32_t b1) {
    asm volatile(
        "mma.sync.aligned.m16n8k16.row.col.f32.f16.f16.f32 "
        "{%0,%1,%2,%3}, {%4,%5,%6,%7}, {%8,%9}, {%0,%1,%2,%3};\n"
        : "+f"(c[0]), "+f"(c[1]), "+f"(c[2]), "+f"(c[3])
        : "r"(a[0]), "r"(a[1]), "r"(a[2]), "r"(a[3]), "r"(b0), "r"(b1));
}

#define LDSM_X4(R0,R1,R2,R3,ADDR)                                              \
    asm volatile("ldmatrix.sync.aligned.m8n8.x4.shared.b16 {%0,%1,%2,%3}, [%4];" \
        : "=r"(R0), "=r"(R1), "=r"(R2), "=r"(R3) : "r"(ADDR))
#define LDSM_X2(R0,R1,ADDR)                                                    \
    asm volatile("ldmatrix.sync.aligned.m8n8.x2.shared.b16 {%0,%1}, [%2];"     \
        : "=r"(R0), "=r"(R1) : "r"(ADDR))
#define LDSM_X2T(R0,R1,ADDR)                                                   \
    asm volatile("ldmatrix.sync.aligned.m8n8.x2.trans.shared.b16 {%0,%1}, [%2];" \
        : "=r"(R0), "=r"(R1) : "r"(ADDR))

// ---------------- RoPE tables (fp64 for accuracy, stored fp32) ---------------
__global__ void rope_table_kernel() {
    int t = blockIdx.x;
    int j = threadIdx.x;  // 0..63
    double inv = exp(-(double)j * (13.815510557964274 / 64.0)); // theta=1e6
    double ang = (double)t * inv;
    g_cos[t * 64 + j] = (float)cos(ang);
    g_sin[t * 64 + j] = (float)sin(ang);
}

// ---------------- fp32 -> fp16 convert ----------------------------------------
__global__ __launch_bounds__(256) void conv_half_kernel(
    const float* __restrict__ in, __half* __restrict__ out, size_t n)
{
    size_t i = ((size_t)blockIdx.x * 256 + threadIdx.x) * 4;
    if (i < n) {
        float4 v = *(const float4*)(in + i);
        __half2 h0 = __floats2half2_rn(v.x, v.y);
        __half2 h1 = __floats2half2_rn(v.z, v.w);
        *(__half2*)(out + i)     = h0;
        *(__half2*)(out + i + 2) = h1;
    }
}

// ---------------- W [K,N] fp32 -> Wt [N,K] fp16 -------------------------------
__global__ __launch_bounds__(256) void wt_half_kernel(
    const float* __restrict__ W, __half* __restrict__ Wt, int K, int N_)
{
    __shared__ float t[32][33];
    int n0 = blockIdx.x * 32, k0 = blockIdx.y * 32;
    int tx = threadIdx.x & 31, ty = threadIdx.x >> 5;   // 32 x 8
    #pragma unroll
    for (int i = 0; i < 32; i += 8)
        t[ty + i][tx] = W[(size_t)(k0 + ty + i) * N_ + n0 + tx];
    __syncthreads();
    #pragma unroll
    for (int i = 0; i < 32; i += 8)
        Wt[(size_t)(n0 + ty + i) * K + k0 + tx] = __float2half(t[tx][ty + i]);
}

// ---------------- fp16 tensor-core GEMM: C[M,N] = A[M,K] @ B[N,K]^T -----------
// A,B fp16 K-major. 128x128 tile, BK=16, 256 threads, 8 warps each 32x64.
#define GAS 24   // smem row stride in halves (12 words: 12g+tg conflict-free)
__global__ __launch_bounds__(256, 2) void gemm_fp16_kernel(
    const __half* __restrict__ A, const __half* __restrict__ Bm,
    float* __restrict__ C, int M, int N_, int K)
{
    __shared__ __half As[128 * GAS];
    __shared__ __half Bs[128 * GAS];

    int tid = threadIdx.x;
    int wid = tid >> 5, lane = tid & 31;
    int g = lane >> 2, tg = lane & 3;
    int warpRow = wid >> 1, warpCol = wid & 1;  // 4 x 2 warps
    int brow = blockIdx.y * 128, bcol = blockIdx.x * 128;

    int row = tid >> 1;            // 0..127
    int seg = (tid & 1) * 8;       // 0 or 8 halves
    const __half* Ap = A  + (size_t)(brow + row) * K + seg;
    const __half* Bp = Bm + (size_t)(bcol + row) * K + seg;

    float acc[2][8][4];
    #pragma unroll
    for (int mi = 0; mi < 2; mi++)
        #pragma unroll
        for (int ni = 0; ni < 8; ni++)
            #pragma unroll
            for (int c = 0; c < 4; c++) acc[mi][ni][c] = 0.f;

    int4 pa = *(const int4*)Ap;
    int4 pb = *(const int4*)Bp;

    for (int k0 = 0; k0 < K; k0 += 16) {
        *(int4*)&As[row * GAS + seg] = pa;
        *(int4*)&Bs[row * GAS + seg] = pb;
        __syncthreads();
        if (k0 + 16 < K) {
            pa = *(const int4*)(Ap + k0 + 16);
            pb = *(const int4*)(Bp + k0 + 16);
        }

        uint32_t af[2][4];
        #pragma unroll
        for (int mi = 0; mi < 2; mi++) {
            int r = warpRow * 32 + mi * 16 + g;
            af[mi][0] = *(uint32_t*)&As[r * GAS + 2 * tg];
            af[mi][1] = *(uint32_t*)&As[(r + 8) * GAS + 2 * tg];
            af[mi][2] = *(uint32_t*)&As[r * GAS + 8 + 2 * tg];
            af[mi][3] = *(uint32_t*)&As[(r + 8) * GAS + 8 + 2 * tg];
        }
        uint32_t bf[8][2];
        #pragma unroll
        for (int ni = 0; ni < 8; ni++) {
            int n = warpCol * 64 + ni * 8 + g;
            bf[ni][0] = *(uint32_t*)&Bs[n * GAS + 2 * tg];
            bf[ni][1] = *(uint32_t*)&Bs[n * GAS + 8 + 2 * tg];
        }
        #pragma unroll
        for (int mi = 0; mi < 2; mi++)
            #pragma unroll
            for (int ni = 0; ni < 8; ni++)
                mma_f16(acc[mi][ni], af[mi], bf[ni][0], bf[ni][1]);
        __syncthreads();
    }

    // epilogue
    #pragma unroll
    for (int mi = 0; mi < 2; mi++) {
        int r0 = brow + warpRow * 32 + mi * 16 + g;
        #pragma unroll
        for (int ni = 0; ni < 8; ni++) {
            int cn = bcol + warpCol * 64 + ni * 8 + tg * 2;
            *(float2*)(C + (size_t)r0 * N_ + cn) = make_float2(acc[mi][ni][0], acc[mi][ni][1]);
            *(float2*)(C + (size_t)(r0 + 8) * N_ + cn) = make_float2(acc[mi][ni][2], acc[mi][ni][3]);
        }
    }
}

// ------------- RMSNorm + RoPE + transpose [b,t,h,d] -> [b,h,t,d] fp16 ---------
__global__ __launch_bounds__(128) void norm_rope_kernel(
    const float* __restrict__ src, __half* __restrict__ dst,
    const float* __restrict__ w, int nheads)
{
    int r = blockIdx.x;              // (b*T+t)*nheads + h
    int d = threadIdx.x;             // 0..127
    int h  = r % nheads;
    int bt = r / nheads;
    int t  = bt % TT;
    int b  = bt / TT;

    float val = src[(size_t)r * HD + d];
    __shared__ float red[4];
    __shared__ float sh[HD];

    float ss = val * val;
    #pragma unroll
    for (int off = 16; off; off >>= 1)
        ss += __shfl_xor_sync(0xffffffffu, ss, off);
    if ((d & 31) == 0) red[d >> 5] = ss;
    __syncthreads();
    float tot = red[0] + red[1] + red[2] + red[3];
    float nv = val * rsqrtf(tot * (1.0f / HD) + 1e-6f) * w[d];
    sh[d] = nv;
    __syncthreads();

    int j = d & 63;
    float c = g_cos[t * 64 + j];
    float s = g_sin[t * 64 + j];
    float other = (d < 64) ? -sh[d + 64] : sh[d - 64];
    float out = nv * c + other * s;

    dst[((size_t)(b * nheads + h) * TT + t) * HD + d] = __float2half(out);
}

// ------------- V transpose [b,t,h,d] -> [b,h,t,d] fp16 ------------------------
__global__ __launch_bounds__(128) void transpose_kernel(
    const float* __restrict__ src, __half* __restrict__ dst, int nheads)
{
    int r = blockIdx.x;
    int d = threadIdx.x;
    int h  = r % nheads;
    int bt = r / nheads;
    int t  = bt % TT;
    int b  = bt / TT;
    dst[((size_t)(b * nheads + h) * TT + t) * HD + d] = __float2half(src[(size_t)r * HD + d]);
}

// ------------- Causal flash attention, fp16 mma + ldmatrix --------------------
// grid (T/64, B*NH), 128 threads (4 warps). BQ=64, BK=64, D=128.
// warp w owns Q rows [w*16, w*16+16).
#define US_STR 136   // halves; 272B rows, /16 = 17 odd -> ldmatrix conflict-free
#define PS_STR 72    // halves; 144B rows, /16 = 9 odd
#define FL_TILE (64 * US_STR)                 // halves per K/V/U tile (8704)
#define FLASH_SMEM (3 * FL_TILE * 2)          // bytes (52224)

__global__ __launch_bounds__(128) void flash_fp16_kernel(
    const __half* __restrict__ Q, const __half* __restrict__ Kt,
    const __half* __restrict__ Vt, __half* __restrict__ ctx)
{
    extern __shared__ __half smh[];
    __half* Ks = smh;
    __half* Vs = smh + FL_TILE;
    __half* Us = smh + 2 * FL_TILE;   // Q stage, later Ps
    __half* Ps = Us;

    int tid = threadIdx.x;
    int wid = tid >> 5, lane = tid & 31;
    int g = lane >> 2, tg = lane & 3;
    int lr = lane & 7;                // ldmatrix row within 8x8
    int lm = (lane >> 3) & 1;         // ldmatrix matrix pair selector
    int lh = lane >> 4;               // high matrix pair (x4)

    int qb = blockIdx.x;              // 0..31
    int bh = blockIdx.y;              // 0..31
    int b = bh / NH, h = bh % NH;
    int kvh = h / (NH / NKV);

    const __half* Qbase = Q  + ((size_t)(b * NH  + h)   * TT + qb * 64) * HD;
    const __half* Kbase = Kt + ((size_t)(b * NKV + kvh) * TT) * HD;
    const __half* Vbase = Vt + ((size_t)(b * NKV + kvh) * TT) * HD;

    uint32_t sK = smem_u32(Ks), sV = smem_u32(Vs), sU = smem_u32(Us), sP = sU;
    int base = wid * 16;

    // ---- stage Q, load fragments ------------------------------------------
    #pragma unroll
    for (int it = 0; it < 8; ++it) {
        int idx = it * 128 + tid;
        int r = idx >> 4;
        int c8 = (idx & 15) * 8;
        *(int4*)&Us[r * US_STR + c8] = *(const int4*)(Qbase + (size_t)r * HD + c8);
    }
    __syncthreads();

    uint32_t qa[8][4];
    #pragma unroll
    for (int ks = 0; ks < 8; ++ks) {
        uint32_t au = sU + (uint32_t)(((base + lr + lm * 8) * US_STR + ks * 16 + lh * 8) * 2);
        LDSM_X4(qa[ks][0], qa[ks][1], qa[ks][2], qa[ks][3], au);
    }

    float o[16][4];
    #pragma unroll
    for (int ni = 0; ni < 16; ni++)
        #pragma unroll
        for (int c = 0; c < 4; c++) o[ni][c] = 0.f;
    float mrow[2] = {-1e30f, -1e30f};
    float lrow[2] = {0.f, 0.f};

    const float scale = 0.08838834764831845f;   // 128^-0.5
    const float L2E = 1.44269504088896f;

    for (int kb = 0; kb <= qb; ++kb) {
        const __half* Kp = Kbase + (size_t)kb * 64 * HD;
        const __half* Vp = Vbase + (size_t)kb * 64 * HD;
        __syncthreads();   // prior iter's reads of Ks/Vs done
        #pragma unroll
        for (int it = 0; it < 8; ++it) {
            int idx = it * 128 + tid;
            int r = idx >> 4;
            int c8 = (idx & 15) * 8;
            *(int4*)&Ks[r * US_STR + c8] = *(const int4*)(Kp + (size_t)r * HD + c8);
            *(int4*)&Vs[r * US_STR + c8] = *(const int4*)(Vp + (size_t)r * HD + c8);
        }
        __syncthreads();

        // ---- S = Q @ K^T -------------------------------------------------
        float s[8][4];
        #pragma unroll
        for (int ni = 0; ni < 8; ni++)
            #pragma unroll
            for (int c = 0; c < 4; c++) s[ni][c] = 0.f;

        #pragma unroll
        for (int ks = 0; ks < 8; ++ks) {
            int kk = ks * 16;
            #pragma unroll
            for (int ni = 0; ni < 8; ni++) {
                uint32_t b0, b1;
                uint32_t ak = sK + (uint32_t)(((ni * 8 + lr) * US_STR + kk + lm * 8) * 2);
                LDSM_X2(b0, b1, ak);
                mma_f16(s[ni], qa[ks], b0, b1);
            }
        }

        // ---- online softmax ----------------------------------------------
        bool diag = (kb == qb);
        int rowA = base + g;
        int rowB = rowA + 8;
        float mA = -1e30f, mB = -1e30f;
        #pragma unroll
        for (int ni = 0; ni < 8; ni++) {
            #pragma unroll
            for (int c = 0; c < 4; c++) {
                float sv = s[ni][c] * scale;
                if (diag) {
                    int kcol = ni * 8 + tg * 2 + (c & 1);
                    int qrow = (c < 2) ? rowA : rowB;
                    if (kcol > qrow) sv = -1e30f;
                }
                s[ni][c] = sv;
            }
            mA = fmaxf(mA, fmaxf(s[ni][0], s[ni][1]));
            mB = fmaxf(mB, fmaxf(s[ni][2], s[ni][3]));
        }
        #pragma unroll
        for (int off = 1; off < 4; off <<= 1) {
            mA = fmaxf(mA, __shfl_xor_sync(0xffffffffu, mA, off));
            mB = fmaxf(mB, __shfl_xor_sync(0xffffffffu, mB, off));
        }
        float mnA = fmaxf(mrow[0], mA);
        float mnB = fmaxf(mrow[1], mB);
        float alA = exp2f((mrow[0] - mnA) * L2E);
        float alB = exp2f((mrow[1] - mnB) * L2E);
        mrow[0] = mnA; mrow[1] = mnB;

        float lA = 0.f, lB = 0.f;
        #pragma unroll
        for (int ni = 0; ni < 8; ni++) {
            s[ni][0] = exp2f((s[ni][0] - mnA) * L2E);
            s[ni][1] = exp2f((s[ni][1] - mnA) * L2E);
            s[ni][2] = exp2f((s[ni][2] - mnB) * L2E);
            s[ni][3] = exp2f((s[ni][3] - mnB) * L2E);
            lA += s[ni][0] + s[ni][1];
            lB += s[ni][2] + s[ni][3];
        }
        #pragma unroll
        for (int off = 1; off < 4; off <<= 1) {
            lA += __shfl_xor_sync(0xffffffffu, lA, off);
            lB += __shfl_xor_sync(0xffffffffu, lB, off);
        }
        lrow[0] = lrow[0] * alA + lA;
        lrow[1] = lrow[1] * alB + lB;
        #pragma unroll
        for (int ni = 0; ni < 16; ni++) {
            o[ni][0] *= alA; o[ni][1] *= alA;
            o[ni][2] *= alB; o[ni][3] *= alB;
        }

        // write P (fp16) — own-warp rows only, so __syncwarp suffices
        #pragma unroll
        for (int ni = 0; ni < 8; ni++) {
            int cn = ni * 8 + tg * 2;
            *(__half2*)&Ps[rowA * PS_STR + cn] = __floats2half2_rn(s[ni][0], s[ni][1]);
            *(__half2*)&Ps[rowB * PS_STR + cn] = __floats2half2_rn(s[ni][2], s[ni][3]);
        }
        __syncwarp();

        // ---- O += P @ V ---------------------------------------------------
        #pragma unroll
        for (int ks = 0; ks < 4; ++ks) {
            int kk = ks * 16;
            uint32_t pa4[4];
            uint32_t ap = sP + (uint32_t)(((base + lr + lm * 8) * PS_STR + kk + lh * 8) * 2);
            LDSM_X4(pa4[0], pa4[1], pa4[2], pa4[3], ap);
            #pragma unroll
            for (int ni = 0; ni < 16; ni++) {
                uint32_t b0, b1;
                uint32_t av = sV + (uint32_t)(((kk + lr + lm * 8) * US_STR + ni * 8) * 2);
                LDSM_X2T(b0, b1, av);
                mma_f16(o[ni], pa4, b0, b1);
            }
        }
    }

    // ---- epilogue: ctx fp16 at [b*T+q, h*HD+d] --------------------------------
    float ivA = 1.0f / lrow[0];
    float ivB = 1.0f / lrow[1];
    int qA = qb * 64 + base + g;
    int qB = qA + 8;
    size_t offA = (size_t)(b * TT + qA) * (NH * HD) + h * HD;
    size_t offB = (size_t)(b * TT + qB) * (NH * HD) + h * HD;
    #pragma unroll
    for (int ni = 0; ni < 16; ni++) {
        int dn = ni * 8 + tg * 2;
        *(__half2*)(ctx + offA + dn) = __floats2half2_rn(o[ni][0] * ivA, o[ni][1] * ivA);
        *(__half2*)(ctx + offB + dn) = __floats2half2_rn(o[ni][2] * ivB, o[ni][3] * ivB);
    }
}

// ---------------------------- launch -----------------------------------------
extern "C" void kernel_launch(void* const* d_in, const int* in_sizes, int n_in,
                              void* d_out, int out_size)
{
    const float* x    = (const float*)d_in[0];
    // d_in[1] = attn_mask (pure causal; applied analytically)
    const float* Wq   = (const float*)d_in[2];
    const float* Wk   = (const float*)d_in[3];
    const float* Wv   = (const float*)d_in[4];
    const float* Wo   = (const float*)d_in[5];
    const float* qnw  = (const float*)d_in[6];
    const float* knw  = (const float*)d_in[7];
    float* out = (float*)d_out;

    float *qraw, *kraw, *vraw;
    __half *qt, *kt, *vt, *xh, *wq, *wk, *wv, *wo, *ctx;
    cudaGetSymbolAddress((void**)&qraw, g_qraw);
    cudaGetSymbolAddress((void**)&kraw, g_kraw);
    cudaGetSymbolAddress((void**)&vraw, g_vraw);
    cudaGetSymbolAddress((void**)&qt,   g_qt);
    cudaGetSymbolAddress((void**)&kt,   g_kt);
    cudaGetSymbolAddress((void**)&vt,   g_vt);
    cudaGetSymbolAddress((void**)&xh,   g_xh);
    cudaGetSymbolAddress((void**)&wq,   g_wq);
    cudaGetSymbolAddress((void**)&wk,   g_wk);
    cudaGetSymbolAddress((void**)&wv,   g_wv);
    cudaGetSymbolAddress((void**)&wo,   g_wo);
    cudaGetSymbolAddress((void**)&ctx,  g_ctx);

    cudaFuncSetAttribute(flash_fp16_kernel, cudaFuncAttributeMaxDynamicSharedMemorySize,
                         FLASH_SMEM);

    // 0: rope table
    rope_table_kernel<<<TT, 64>>>();
    // 1: x -> fp16
    conv_half_kernel<<<(unsigned)(((size_t)MM * HH / 4 + 255) / 256), 256>>>(
        x, xh, (size_t)MM * HH);
    // 2-4: W^T fp16
    wt_half_kernel<<<dim3(2048 / 32, 2048 / 32), 256>>>(Wq, wq, 2048, 2048);
    wt_half_kernel<<<dim3(1024 / 32, 2048 / 32), 256>>>(Wk, wk, 2048, 1024);
    wt_half_kernel<<<dim3(1024 / 32, 2048 / 32), 256>>>(Wv, wv, 2048, 1024);
    // 5-7: QKV projections (fp16 tensor cores)  [slot 5 = ncu capture]
    gemm_fp16_kernel<<<dim3(2048 / 128, MM / 128), 256>>>(xh, wq, qraw, MM, 2048, HH);
    gemm_fp16_kernel<<<dim3(1024 / 128, MM / 128), 256>>>(xh, wk, kraw, MM, 1024, HH);
    gemm_fp16_kernel<<<dim3(1024 / 128, MM / 128), 256>>>(xh, wv, vraw, MM, 1024, HH);
    // 8-10: RMSNorm/RoPE/transpose -> fp16
    norm_rope_kernel<<<BB * TT * NH, 128>>>(qraw, qt, qnw, NH);
    norm_rope_kernel<<<BB * TT * NKV, 128>>>(kraw, kt, knw, NKV);
    transpose_kernel<<<BB * TT * NKV, 128>>>(vraw, vt, NKV);
    // 11: Wo^T fp16
    wt_half_kernel<<<dim3(2048 / 32, 2048 / 32), 256>>>(Wo, wo, 2048, 2048);
    // 12: flash attention (fp16 mma), ctx fp16
    flash_fp16_kernel<<<dim3(TT / 64, BB * NH), 128, FLASH_SMEM>>>(qt, kt, vt, ctx);
    // 13: output projection
    gemm_fp16_kernel<<<dim3(2048 / 128, MM / 128), 256>>>(ctx, wo, out, MM, 2048, HH);
}

// round 6
// speedup vs baseline: 4.9558x; 1.0421x over previous
#include <cuda_runtime.h>
#include <cuda_fp16.h>
#include <cstdint>
#include <cstddef>
#include <math.h>

// Problem constants
#define BB   2
#define TT   2048
#define HH   2048
#define NH   16
#define NKV  8
#define HD   128
#define MM   (BB*TT)            // 4096 rows

// ---------------- scratch (static device globals; no allocation) -------------
__device__ float g_qkvraw[(size_t)MM * 4096];      // [b*T+t, {Q:0..2047,K:2048..3071,V:3072..4095}]
__device__ __half g_qt[(size_t)BB * NH * TT * HD]; // [b,h,t,d] fp16
__device__ __half g_kt[(size_t)BB * NKV * TT * HD];
__device__ __half g_vt[(size_t)BB * NKV * TT * HD];
__device__ __half g_xh[(size_t)MM * HH];           // x fp16
__device__ __half g_wqkv[(size_t)4096 * 2048];     // [N=4096, K=2048] fp16 (Q|K|V rows)
__device__ __half g_wo[(size_t)2048 * 2048];       // Wo^T [N,K] fp16
__device__ __half g_ctx[(size_t)MM * HH];          // [b*T+t, h*HD+d] fp16
__device__ float g_cos[TT * 64];
__device__ float g_sin[TT * 64];

// ---------------- helpers ----------------------------------------------------
__device__ __forceinline__ uint32_t smem_u32(const void* p) {
    uint32_t a;
    asm("{ .reg .u64 t; cvta.to.shared.u64 t, %1; cvt.u32.u64 %0, t; }" : "=r"(a) : "l"(p));
    return a;
}

__device__ __forceinline__ void mma_f16(float c[4], const uint32_t a[4],
                                        uint32_t b0, uint32_t b1) {
    asm volatile(
        "mma.sync.aligned.m16n8k16.row.col.f32.f16.f16.f32 "
        "{%0,%1,%2,%3}, {%4,%5,%6,%7}, {%8,%9}, {%0,%1,%2,%3};\n"
        : "+f"(c[0]), "+f"(c[1]), "+f"(c[2]), "+f"(c[3])
        : "r"(a[0]), "r"(a[1]), "r"(a[2]), "r"(a[3]), "r"(b0), "r"(b1));
}

#define LDSM_X4(R0,R1,R2,R3,ADDR)                                              \
    asm volatile("ldmatrix.sync.aligned.m8n8.x4.shared.b16 {%0,%1,%2,%3}, [%4];" \
        : "=r"(R0), "=r"(R1), "=r"(R2), "=r"(R3) : "r"(ADDR))
#define LDSM_X2(R0,R1,ADDR)                                                    \
    asm volatile("ldmatrix.sync.aligned.m8n8.x2.shared.b16 {%0,%1}, [%2];"     \
        : "=r"(R0), "=r"(R1) : "r"(ADDR))
#define LDSM_X2T(R0,R1,ADDR)                                                   \
    asm volatile("ldmatrix.sync.aligned.m8n8.x2.trans.shared.b16 {%0,%1}, [%2];" \
        : "=r"(R0), "=r"(R1) : "r"(ADDR))

// ---------------- RoPE tables (fp64 for accuracy, stored fp32) ---------------
__global__ void rope_table_kernel() {
    int t = blockIdx.x;
    int j = threadIdx.x;  // 0..63
    double inv = exp(-(double)j * (13.815510557964274 / 64.0)); // theta=1e6
    double ang = (double)t * inv;
    g_cos[t * 64 + j] = (float)cos(ang);
    g_sin[t * 64 + j] = (float)sin(ang);
}

// ---------------- fp32 -> fp16 convert ----------------------------------------
__global__ __launch_bounds__(256) void conv_half_kernel(
    const float* __restrict__ in, __half* __restrict__ out, size_t n)
{
    size_t i = ((size_t)blockIdx.x * 256 + threadIdx.x) * 4;
    if (i < n) {
        float4 v = *(const float4*)(in + i);
        *(__half2*)(out + i)     = __floats2half2_rn(v.x, v.y);
        *(__half2*)(out + i + 2) = __floats2half2_rn(v.z, v.w);
    }
}

// ---------------- W [K,N] fp32 -> Wt [N,K] fp16 -------------------------------
__global__ __launch_bounds__(256) void wt_half_kernel(
    const float* __restrict__ W, __half* __restrict__ Wt, int K, int N_)
{
    __shared__ float t[32][33];
    int n0 = blockIdx.x * 32, k0 = blockIdx.y * 32;
    int tx = threadIdx.x & 31, ty = threadIdx.x >> 5;   // 32 x 8
    #pragma unroll
    for (int i = 0; i < 32; i += 8)
        t[ty + i][tx] = W[(size_t)(k0 + ty + i) * N_ + n0 + tx];
    __syncthreads();
    #pragma unroll
    for (int i = 0; i < 32; i += 8)
        Wt[(size_t)(n0 + ty + i) * K + k0 + tx] = __float2half(t[tx][ty + i]);
}

// ---------------- fp16 tensor-core GEMM: C[M,N] = A[M,K] @ B[N,K]^T -----------
// Double-buffered smem, BK=16, 128x128 tile, 256 threads, 8 warps each 32x64.
#define GAS 24   // smem row stride in halves
__global__ __launch_bounds__(256, 2) void gemm_fp16_kernel(
    const __half* __restrict__ A, const __half* __restrict__ Bm,
    float* __restrict__ C, int M, int N_, int K)
{
    __shared__ __half As[2][128 * GAS];
    __shared__ __half Bs[2][128 * GAS];

    int tid = threadIdx.x;
    int wid = tid >> 5, lane = tid & 31;
    int g = lane >> 2, tg = lane & 3;
    int warpRow = wid >> 1, warpCol = wid & 1;  // 4 x 2 warps
    int brow = blockIdx.y * 128, bcol = blockIdx.x * 128;

    int row = tid >> 1;            // 0..127
    int seg = (tid & 1) * 8;       // 0 or 8 halves
    const __half* Ap = A  + (size_t)(brow + row) * K + seg;
    const __half* Bp = Bm + (size_t)(bcol + row) * K + seg;

    float acc[2][8][4];
    #pragma unroll
    for (int mi = 0; mi < 2; mi++)
        #pragma unroll
        for (int ni = 0; ni < 8; ni++)
            #pragma unroll
            for (int c = 0; c < 4; c++) acc[mi][ni][c] = 0.f;

    // prime buffer 0
    {
        int4 pa = *(const int4*)Ap;
        int4 pb = *(const int4*)Bp;
        *(int4*)&As[0][row * GAS + seg] = pa;
        *(int4*)&Bs[0][row * GAS + seg] = pb;
    }
    __syncthreads();

    int buf = 0;
    for (int k0 = 0; k0 < K; k0 += 16) {
        int4 pa, pb;
        bool more = (k0 + 16 < K);
        if (more) {
            pa = *(const int4*)(Ap + k0 + 16);
            pb = *(const int4*)(Bp + k0 + 16);
        }

        const __half* Ab = As[buf];
        const __half* Bb = Bs[buf];
        uint32_t af[2][4];
        #pragma unroll
        for (int mi = 0; mi < 2; mi++) {
            int r = warpRow * 32 + mi * 16 + g;
            af[mi][0] = *(const uint32_t*)&Ab[r * GAS + 2 * tg];
            af[mi][1] = *(const uint32_t*)&Ab[(r + 8) * GAS + 2 * tg];
            af[mi][2] = *(const uint32_t*)&Ab[r * GAS + 8 + 2 * tg];
            af[mi][3] = *(const uint32_t*)&Ab[(r + 8) * GAS + 8 + 2 * tg];
        }
        uint32_t bf[8][2];
        #pragma unroll
        for (int ni = 0; ni < 8; ni++) {
            int n = warpCol * 64 + ni * 8 + g;
            bf[ni][0] = *(const uint32_t*)&Bb[n * GAS + 2 * tg];
            bf[ni][1] = *(const uint32_t*)&Bb[n * GAS + 8 + 2 * tg];
        }
        #pragma unroll
        for (int mi = 0; mi < 2; mi++)
            #pragma unroll
            for (int ni = 0; ni < 8; ni++)
                mma_f16(acc[mi][ni], af[mi], bf[ni][0], bf[ni][1]);

        if (more) {
            *(int4*)&As[buf ^ 1][row * GAS + seg] = pa;
            *(int4*)&Bs[buf ^ 1][row * GAS + seg] = pb;
        }
        __syncthreads();
        buf ^= 1;
    }

    // epilogue
    #pragma unroll
    for (int mi = 0; mi < 2; mi++) {
        int r0 = brow + warpRow * 32 + mi * 16 + g;
        #pragma unroll
        for (int ni = 0; ni < 8; ni++) {
            int cn = bcol + warpCol * 64 + ni * 8 + tg * 2;
            *(float2*)(C + (size_t)r0 * N_ + cn) = make_float2(acc[mi][ni][0], acc[mi][ni][1]);
            *(float2*)(C + (size_t)(r0 + 8) * N_ + cn) = make_float2(acc[mi][ni][2], acc[mi][ni][3]);
        }
    }
}

// ------------- RMSNorm + RoPE + transpose -> [b,h,t,d] fp16 -------------------
// src rows have stride srcStride; head data at src[row*srcStride + d].
__global__ __launch_bounds__(128) void norm_rope_kernel(
    const float* __restrict__ src, __half* __restrict__ dst,
    const float* __restrict__ w, int nheads, int srcStride)
{
    int r = blockIdx.x;              // (b*T+t)*nheads + h
    int d = threadIdx.x;             // 0..127
    int h  = r % nheads;
    int bt = r / nheads;
    int t  = bt % TT;
    int b  = bt / TT;

    float val = src[(size_t)bt * srcStride + h * HD + d];
    __shared__ float red[4];
    __shared__ float sh[HD];

    float ss = val * val;
    #pragma unroll
    for (int off = 16; off; off >>= 1)
        ss += __shfl_xor_sync(0xffffffffu, ss, off);
    if ((d & 31) == 0) red[d >> 5] = ss;
    __syncthreads();
    float tot = red[0] + red[1] + red[2] + red[3];
    float nv = val * rsqrtf(tot * (1.0f / HD) + 1e-6f) * w[d];
    sh[d] = nv;
    __syncthreads();

    int j = d & 63;
    float c = g_cos[t * 64 + j];
    float s = g_sin[t * 64 + j];
    float other = (d < 64) ? -sh[d + 64] : sh[d - 64];
    float out = nv * c + other * s;

    dst[((size_t)(b * nheads + h) * TT + t) * HD + d] = __float2half(out);
}

// ------------- V transpose -> [b,h,t,d] fp16 ----------------------------------
__global__ __launch_bounds__(128) void transpose_kernel(
    const float* __restrict__ src, __half* __restrict__ dst, int nheads, int srcStride)
{
    int r = blockIdx.x;
    int d = threadIdx.x;
    int h  = r % nheads;
    int bt = r / nheads;
    int t  = bt % TT;
    int b  = bt / TT;
    dst[((size_t)(b * nheads + h) * TT + t) * HD + d] =
        __float2half(src[(size_t)bt * srcStride + h * HD + d]);
}

// ------------- Causal flash attention, fp16 mma + ldmatrix, 2 heads/CTA -------
// grid (T/64, B*NKV), 256 threads (8 warps). Warps 0-3: head 2*kvh, 4-7: 2*kvh+1.
// Shared K/V tiles (GQA reuse). BQ=64 per head, BK=64, D=128.
#define US_STR 136   // halves; 272B rows -> ldmatrix conflict-free
#define PS_STR 72
#define FL_KV  (64 * US_STR)                  // halves per K or V tile
#define FL_U   (128 * US_STR)                 // two heads' Q (later two P bufs)
#define FLASH_SMEM ((2 * FL_KV + FL_U) * 2)   // bytes

__global__ __launch_bounds__(256) void flash_fp16_kernel(
    const __half* __restrict__ Q, const __half* __restrict__ Kt,
    const __half* __restrict__ Vt, __half* __restrict__ ctx)
{
    extern __shared__ __half smh[];
    __half* Ks = smh;
    __half* Vs = smh + FL_KV;
    __half* Us = smh + 2 * FL_KV;     // Q stage (128 rows), later P (2 x 64 rows)
    __half* Ps = Us;

    int tid = threadIdx.x;
    int wid = tid >> 5, lane = tid & 31;
    int g = lane >> 2, tg = lane & 3;
    int lr = lane & 7;
    int lm = (lane >> 3) & 1;
    int lh = lane >> 4;

    int hw = wid >> 2;                // head within CTA (0/1)
    int w4 = wid & 3;                 // warp within head
    int base = w4 * 16;               // q-row base within head tile

    int qb = blockIdx.x;              // 0..31
    int bk = blockIdx.y;              // 0..(BB*NKV-1)
    int b = bk / NKV, kvh = bk % NKV;
    int h = kvh * 2 + hw;

    const __half* Qbase = Q  + ((size_t)(b * NH  + h)   * TT + qb * 64) * HD;
    const __half* Kbase = Kt + ((size_t)(b * NKV + kvh) * TT) * HD;
    const __half* Vbase = Vt + ((size_t)(b * NKV + kvh) * TT) * HD;

    uint32_t sK = smem_u32(Ks), sV = smem_u32(Vs), sU = smem_u32(Us), sP = sU;

    // ---- stage both heads' Q (head hw rows at offset hw*64) ------------------
    {
        // each half of the CTA loads its own head's Q tile
        const __half* Qh = Q + ((size_t)(b * NH + kvh * 2 + hw) * TT + qb * 64) * HD;
        int t128 = tid & 127;         // 0..127 within head-half
        #pragma unroll
        for (int it = 0; it < 8; ++it) {
            int idx = it * 128 + t128;
            int r = idx >> 4;
            int c8 = (idx & 15) * 8;
            *(int4*)&Us[(hw * 64 + r) * US_STR + c8] =
                *(const int4*)(Qh + (size_t)r * HD + c8);
        }
    }
    __syncthreads();

    uint32_t qa[8][4];
    #pragma unroll
    for (int ks = 0; ks < 8; ++ks) {
        uint32_t au = sU + (uint32_t)(((hw * 64 + base + lr + lm * 8) * US_STR + ks * 16 + lh * 8) * 2);
        LDSM_X4(qa[ks][0], qa[ks][1], qa[ks][2], qa[ks][3], au);
    }

    float o[16][4];
    #pragma unroll
    for (int ni = 0; ni < 16; ni++)
        #pragma unroll
        for (int c = 0; c < 4; c++) o[ni][c] = 0.f;
    float mrow[2] = {-1e30f, -1e30f};
    float lrow[2] = {0.f, 0.f};

    const float scale = 0.08838834764831845f;   // 128^-0.5
    const float L2E = 1.44269504088896f;

    for (int kb = 0; kb <= qb; ++kb) {
        const __half* Kp = Kbase + (size_t)kb * 64 * HD;
        const __half* Vp = Vbase + (size_t)kb * 64 * HD;
        __syncthreads();   // prior iter's reads of Ks/Vs done (both heads)
        #pragma unroll
        for (int it = 0; it < 4; ++it) {
            int idx = it * 256 + tid;
            int r = idx >> 4;
            int c8 = (idx & 15) * 8;
            *(int4*)&Ks[r * US_STR + c8] = *(const int4*)(Kp + (size_t)r * HD + c8);
            *(int4*)&Vs[r * US_STR + c8] = *(const int4*)(Vp + (size_t)r * HD + c8);
        }
        __syncthreads();

        // ---- S = Q @ K^T -----------------------------------------------------
        float s[8][4];
        #pragma unroll
        for (int ni = 0; ni < 8; ni++)
            #pragma unroll
            for (int c = 0; c < 4; c++) s[ni][c] = 0.f;

        #pragma unroll
        for (int ks = 0; ks < 8; ++ks) {
            int kk = ks * 16;
            #pragma unroll
            for (int ni = 0; ni < 8; ni++) {
                uint32_t b0, b1;
                uint32_t ak = sK + (uint32_t)(((ni * 8 + lr) * US_STR + kk + lm * 8) * 2);
                LDSM_X2(b0, b1, ak);
                mma_f16(s[ni], qa[ks], b0, b1);
            }
        }

        // ---- online softmax --------------------------------------------------
        bool diag = (kb == qb);
        int rowA = base + g;          // within head tile
        int rowB = rowA + 8;
        float mA = -1e30f, mB = -1e30f;
        #pragma unroll
        for (int ni = 0; ni < 8; ni++) {
            #pragma unroll
            for (int c = 0; c < 4; c++) {
                float sv = s[ni][c] * scale;
                if (diag) {
                    int kcol = ni * 8 + tg * 2 + (c & 1);
                    int qrow = (c < 2) ? rowA : rowB;
                    if (kcol > qrow) sv = -1e30f;
                }
                s[ni][c] = sv;
            }
            mA = fmaxf(mA, fmaxf(s[ni][0], s[ni][1]));
            mB = fmaxf(mB, fmaxf(s[ni][2], s[ni][3]));
        }
        #pragma unroll
        for (int off = 1; off < 4; off <<= 1) {
            mA = fmaxf(mA, __shfl_xor_sync(0xffffffffu, mA, off));
            mB = fmaxf(mB, __shfl_xor_sync(0xffffffffu, mB, off));
        }
        float mnA = fmaxf(mrow[0], mA);
        float mnB = fmaxf(mrow[1], mB);
        float alA = exp2f((mrow[0] - mnA) * L2E);
        float alB = exp2f((mrow[1] - mnB) * L2E);
        mrow[0] = mnA; mrow[1] = mnB;

        float lA = 0.f, lB = 0.f;
        #pragma unroll
        for (int ni = 0; ni < 8; ni++) {
            s[ni][0] = exp2f((s[ni][0] - mnA) * L2E);
            s[ni][1] = exp2f((s[ni][1] - mnA) * L2E);
            s[ni][2] = exp2f((s[ni][2] - mnB) * L2E);
            s[ni][3] = exp2f((s[ni][3] - mnB) * L2E);
            lA += s[ni][0] + s[ni][1];
            lB += s[ni][2] + s[ni][3];
        }
        #pragma unroll
        for (int off = 1; off < 4; off <<= 1) {
            lA += __shfl_xor_sync(0xffffffffu, lA, off);
            lB += __shfl_xor_sync(0xffffffffu, lB, off);
        }
        lrow[0] = lrow[0] * alA + lA;
        lrow[1] = lrow[1] * alB + lB;
        #pragma unroll
        for (int ni = 0; ni < 16; ni++) {
            o[ni][0] *= alA; o[ni][1] *= alA;
            o[ni][2] *= alB; o[ni][3] *= alB;
        }

        // write P (fp16) — own-warp rows only; head offset hw*64
        int prowA = hw * 64 + rowA;
        int prowB = hw * 64 + rowB;
        #pragma unroll
        for (int ni = 0; ni < 8; ni++) {
            int cn = ni * 8 + tg * 2;
            *(__half2*)&Ps[prowA * PS_STR + cn] = __floats2half2_rn(s[ni][0], s[ni][1]);
            *(__half2*)&Ps[prowB * PS_STR + cn] = __floats2half2_rn(s[ni][2], s[ni][3]);
        }
        __syncwarp();

        // ---- O += P @ V ------------------------------------------------------
        #pragma unroll
        for (int ks = 0; ks < 4; ++ks) {
            int kk = ks * 16;
            uint32_t pa4[4];
            uint32_t ap = sP + (uint32_t)(((hw * 64 + base + lr + lm * 8) * PS_STR + kk + lh * 8) * 2);
            LDSM_X4(pa4[0], pa4[1], pa4[2], pa4[3], ap);
            #pragma unroll
            for (int ni = 0; ni < 16; ni++) {
                uint32_t b0, b1;
                uint32_t av = sV + (uint32_t)(((kk + lr + lm * 8) * US_STR + ni * 8) * 2);
                LDSM_X2T(b0, b1, av);
                mma_f16(o[ni], pa4, b0, b1);
            }
        }
    }

    // ---- epilogue: ctx fp16 at [b*T+q, h*HD+d] --------------------------------
    float ivA = 1.0f / lrow[0];
    float ivB = 1.0f / lrow[1];
    int qA = qb * 64 + base + g;
    int qB = qA + 8;
    size_t offA = (size_t)(b * TT + qA) * (NH * HD) + h * HD;
    size_t offB = (size_t)(b * TT + qB) * (NH * HD) + h * HD;
    #pragma unroll
    for (int ni = 0; ni < 16; ni++) {
        int dn = ni * 8 + tg * 2;
        *(__half2*)(ctx + offA + dn) = __floats2half2_rn(o[ni][0] * ivA, o[ni][1] * ivA);
        *(__half2*)(ctx + offB + dn) = __floats2half2_rn(o[ni][2] * ivB, o[ni][3] * ivB);
    }
}

// ---------------------------- launch -----------------------------------------
extern "C" void kernel_launch(void* const* d_in, const int* in_sizes, int n_in,
                              void* d_out, int out_size)
{
    const float* x    = (const float*)d_in[0];
    // d_in[1] = attn_mask (pure causal; applied analytically)
    const float* Wq   = (const float*)d_in[2];
    const float* Wk   = (const float*)d_in[3];
    const float* Wv   = (const float*)d_in[4];
    const float* Wo   = (const float*)d_in[5];
    const float* qnw  = (const float*)d_in[6];
    const float* knw  = (const float*)d_in[7];
    float* out = (float*)d_out;

    float *qkvraw;
    __half *qt, *kt, *vt, *xh, *wqkv, *wo, *ctx;
    cudaGetSymbolAddress((void**)&qkvraw, g_qkvraw);
    cudaGetSymbolAddress((void**)&qt,   g_qt);
    cudaGetSymbolAddress((void**)&kt,   g_kt);
    cudaGetSymbolAddress((void**)&vt,   g_vt);
    cudaGetSymbolAddress((void**)&xh,   g_xh);
    cudaGetSymbolAddress((void**)&wqkv, g_wqkv);
    cudaGetSymbolAddress((void**)&wo,   g_wo);
    cudaGetSymbolAddress((void**)&ctx,  g_ctx);

    cudaFuncSetAttribute(flash_fp16_kernel, cudaFuncAttributeMaxDynamicSharedMemorySize,
                         FLASH_SMEM);

    // 0: rope table
    rope_table_kernel<<<TT, 64>>>();
    // 1: x -> fp16
    conv_half_kernel<<<(unsigned)(((size_t)MM * HH / 4 + 255) / 256), 256>>>(
        x, xh, (size_t)MM * HH);
    // 2-5: W^T fp16 (QKV into one buffer, then Wo)
    wt_half_kernel<<<dim3(2048 / 32, 2048 / 32), 256>>>(Wq, wqkv, 2048, 2048);
    wt_half_kernel<<<dim3(1024 / 32, 2048 / 32), 256>>>(Wk, wqkv + (size_t)2048 * 2048, 2048, 1024);
    wt_half_kernel<<<dim3(1024 / 32, 2048 / 32), 256>>>(Wv, wqkv + (size_t)3072 * 2048, 2048, 1024);
    wt_half_kernel<<<dim3(2048 / 32, 2048 / 32), 256>>>(Wo, wo, 2048, 2048);
    // 6: fused QKV projection (N=4096)
    gemm_fp16_kernel<<<dim3(4096 / 128, MM / 128), 256>>>(xh, wqkv, qkvraw, MM, 4096, HH);
    // 7-9: RMSNorm/RoPE/transpose -> fp16
    norm_rope_kernel<<<BB * TT * NH, 128>>>(qkvraw, qt, qnw, NH, 4096);
    norm_rope_kernel<<<BB * TT * NKV, 128>>>(qkvraw + 2048, kt, knw, NKV, 4096);
    transpose_kernel<<<BB * TT * NKV, 128>>>(qkvraw + 3072, vt, NKV, 4096);
    // 10: flash attention (fp16 mma, 2 GQA heads/CTA)
    flash_fp16_kernel<<<dim3(TT / 64, BB * NKV), 256, FLASH_SMEM>>>(qt, kt, vt, ctx);
    // 11: output projection
    gemm_fp16_kernel<<<dim3(2048 / 128, MM / 128), 256>>>(ctx, wo, out, MM, 2048, HH);
}

// round 7
// speedup vs baseline: 5.9109x; 1.1927x over previous
#include <cuda_runtime.h>
#include <cuda_fp16.h>
#include <cstdint>
#include <cstddef>
#include <math.h>

// Problem constants
#define BB   2
#define TT   2048
#define HH   2048
#define NH   16
#define NKV  8
#define HD   128
#define MM   (BB*TT)            // 4096 rows

// ---------------- scratch (static device globals; no allocation) -------------
__device__ float g_qkvraw[(size_t)MM * 4096];      // [b*T+t, {Q|K|V}]
__device__ __half g_qt[(size_t)BB * NH * TT * HD]; // [b,h,t,d] fp16
__device__ __half g_kt[(size_t)BB * NKV * TT * HD];
__device__ __half g_vt[(size_t)BB * NKV * TT * HD];
__device__ __half g_xh[(size_t)MM * HH];           // x fp16
__device__ __half g_wqkv[(size_t)4096 * 2048];     // [N=4096, K=2048] fp16 (Q|K|V rows)
__device__ __half g_wo[(size_t)2048 * 2048];       // Wo^T [N,K] fp16
__device__ __half g_ctx[(size_t)MM * HH];          // [b*T+t, h*HD+d] fp16
__device__ float g_cos[TT * 64];
__device__ float g_sin[TT * 64];

// ---------------- helpers ----------------------------------------------------
__device__ __forceinline__ uint32_t smem_u32(const void* p) {
    uint32_t a;
    asm("{ .reg .u64 t; cvta.to.shared.u64 t, %1; cvt.u32.u64 %0, t; }" : "=r"(a) : "l"(p));
    return a;
}

__device__ __forceinline__ void mma_f16(float c[4], const uint32_t a[4],
                                        uint32_t b0, uint32_t b1) {
    asm volatile(
        "mma.sync.aligned.m16n8k16.row.col.f32.f16.f16.f32 "
        "{%0,%1,%2,%3}, {%4,%5,%6,%7}, {%8,%9}, {%0,%1,%2,%3};\n"
        : "+f"(c[0]), "+f"(c[1]), "+f"(c[2]), "+f"(c[3])
        : "r"(a[0]), "r"(a[1]), "r"(a[2]), "r"(a[3]), "r"(b0), "r"(b1));
}

#define LDSM_X4(R0,R1,R2,R3,ADDR)                                              \
    asm volatile("ldmatrix.sync.aligned.m8n8.x4.shared.b16 {%0,%1,%2,%3}, [%4];" \
        : "=r"(R0), "=r"(R1), "=r"(R2), "=r"(R3) : "r"(ADDR))
#define LDSM_X2(R0,R1,ADDR)                                                    \
    asm volatile("ldmatrix.sync.aligned.m8n8.x2.shared.b16 {%0,%1}, [%2];"     \
        : "=r"(R0), "=r"(R1) : "r"(ADDR))
#define LDSM_X2T(R0,R1,ADDR)                                                   \
    asm volatile("ldmatrix.sync.aligned.m8n8.x2.trans.shared.b16 {%0,%1}, [%2];" \
        : "=r"(R0), "=r"(R1) : "r"(ADDR))

// ---------------- RoPE tables (fp64 for accuracy, stored fp32) ---------------
__global__ void rope_table_kernel() {
    int t = blockIdx.x;
    int j = threadIdx.x;  // 0..63
    double inv = exp(-(double)j * (13.815510557964274 / 64.0)); // theta=1e6
    double ang = (double)t * inv;
    g_cos[t * 64 + j] = (float)cos(ang);
    g_sin[t * 64 + j] = (float)sin(ang);
}

// ---------------- fp32 -> fp16 convert ----------------------------------------
__global__ __launch_bounds__(256) void conv_half_kernel(
    const float* __restrict__ in, __half* __restrict__ out, size_t n)
{
    size_t i = ((size_t)blockIdx.x * 256 + threadIdx.x) * 4;
    if (i < n) {
        float4 v = *(const float4*)(in + i);
        *(__half2*)(out + i)     = __floats2half2_rn(v.x, v.y);
        *(__half2*)(out + i + 2) = __floats2half2_rn(v.z, v.w);
    }
}

// ---------------- W [K,N] fp32 -> Wt [N,K] fp16 -------------------------------
__global__ __launch_bounds__(256) void wt_half_kernel(
    const float* __restrict__ W, __half* __restrict__ Wt, int K, int N_)
{
    __shared__ float t[32][33];
    int n0 = blockIdx.x * 32, k0 = blockIdx.y * 32;
    int tx = threadIdx.x & 31, ty = threadIdx.x >> 5;   // 32 x 8
    #pragma unroll
    for (int i = 0; i < 32; i += 8)
        t[ty + i][tx] = W[(size_t)(k0 + ty + i) * N_ + n0 + tx];
    __syncthreads();
    #pragma unroll
    for (int i = 0; i < 32; i += 8)
        Wt[(size_t)(n0 + ty + i) * K + k0 + tx] = __float2half(t[tx][ty + i]);
}

// ---------------- fp16 tensor-core GEMM: C[M,N] = A[M,K] @ B[N,K]^T -----------
// BK=32, double-buffered smem, ldmatrix fragment loads.
// 128x128 tile, 256 threads, 8 warps each 32x64.
#define GAS 40   // smem row stride in halves (80B = 5x16B, odd -> ldmatrix clean)
#define GSTG (128 * GAS)   // halves per tile per stage
__global__ __launch_bounds__(256, 2) void gemm_fp16_kernel(
    const __half* __restrict__ A, const __half* __restrict__ Bm,
    float* __restrict__ C, int M, int N_, int K)
{
    __shared__ __half As[2 * GSTG];
    __shared__ __half Bs[2 * GSTG];

    int tid = threadIdx.x;
    int wid = tid >> 5, lane = tid & 31;
    int g = lane >> 2, tg = lane & 3;
    int lr = lane & 7;                 // ldmatrix row
    int lm = (lane >> 3) & 1;          // A: row-half selector
    int lh = lane >> 4;                // A: k-half selector
    int sel = lane >> 3;               // B: 0..3
    int warpRow = wid >> 1, warpCol = wid & 1;  // 4 x 2 warps
    int brow = blockIdx.y * 128, bcol = blockIdx.x * 128;

    // global-load mapping: 512 int4 per tile per stage; 2 per thread
    int rowL[2], segL[2];
    #pragma unroll
    for (int it = 0; it < 2; ++it) {
        int idx = it * 256 + tid;
        rowL[it] = idx >> 2;
        segL[it] = (idx & 3) * 8;
    }
    const __half* ApL[2];
    const __half* BpL[2];
    #pragma unroll
    for (int it = 0; it < 2; ++it) {
        ApL[it] = A  + (size_t)(brow + rowL[it]) * K + segL[it];
        BpL[it] = Bm + (size_t)(bcol + rowL[it]) * K + segL[it];
    }

    uint32_t sA = smem_u32(As), sB = smem_u32(Bs);

    float acc[2][8][4];
    #pragma unroll
    for (int mi = 0; mi < 2; mi++)
        #pragma unroll
        for (int ni = 0; ni < 8; ni++)
            #pragma unroll
            for (int c = 0; c < 4; c++) acc[mi][ni][c] = 0.f;

    // prime stage 0
    #pragma unroll
    for (int it = 0; it < 2; ++it) {
        *(int4*)&As[rowL[it] * GAS + segL[it]] = *(const int4*)ApL[it];
        *(int4*)&Bs[rowL[it] * GAS + segL[it]] = *(const int4*)BpL[it];
    }
    __syncthreads();

    int buf = 0;
    for (int k0 = 0; k0 < K; k0 += 32) {
        int4 pa[2], pb[2];
        bool more = (k0 + 32 < K);
        if (more) {
            #pragma unroll
            for (int it = 0; it < 2; ++it) {
                pa[it] = *(const int4*)(ApL[it] + k0 + 32);
                pb[it] = *(const int4*)(BpL[it] + k0 + 32);
            }
        }

        uint32_t bA = sA + buf * (GSTG * 2);
        uint32_t bB = sB + buf * (GSTG * 2);
        #pragma unroll
        for (int ks = 0; ks < 2; ++ks) {
            int kk = ks * 16;
            uint32_t af[2][4];
            #pragma unroll
            for (int mi = 0; mi < 2; mi++) {
                uint32_t addr = bA + (uint32_t)(((warpRow * 32 + mi * 16 + lr + lm * 8) * GAS
                                                 + kk + lh * 8) * 2);
                LDSM_X4(af[mi][0], af[mi][1], af[mi][2], af[mi][3], addr);
            }
            uint32_t bf[8][2];
            #pragma unroll
            for (int nb = 0; nb < 4; nb++) {
                int n0 = warpCol * 64 + nb * 16;
                uint32_t addr = bB + (uint32_t)(((n0 + lr + (sel >> 1) * 8) * GAS
                                                 + kk + (sel & 1) * 8) * 2);
                LDSM_X4(bf[2 * nb][0], bf[2 * nb][1], bf[2 * nb + 1][0], bf[2 * nb + 1][1], addr);
            }
            #pragma unroll
            for (int mi = 0; mi < 2; mi++)
                #pragma unroll
                for (int ni = 0; ni < 8; ni++)
                    mma_f16(acc[mi][ni], af[mi], bf[ni][0], bf[ni][1]);
        }

        if (more) {
            __half* Ad = As + (buf ^ 1) * GSTG;
            __half* Bd = Bs + (buf ^ 1) * GSTG;
            #pragma unroll
            for (int it = 0; it < 2; ++it) {
                *(int4*)&Ad[rowL[it] * GAS + segL[it]] = pa[it];
                *(int4*)&Bd[rowL[it] * GAS + segL[it]] = pb[it];
            }
        }
        __syncthreads();
        buf ^= 1;
    }

    // epilogue
    #pragma unroll
    for (int mi = 0; mi < 2; mi++) {
        int r0 = brow + warpRow * 32 + mi * 16 + g;
        #pragma unroll
        for (int ni = 0; ni < 8; ni++) {
            int cn = bcol + warpCol * 64 + ni * 8 + tg * 2;
            *(float2*)(C + (size_t)r0 * N_ + cn) = make_float2(acc[mi][ni][0], acc[mi][ni][1]);
            *(float2*)(C + (size_t)(r0 + 8) * N_ + cn) = make_float2(acc[mi][ni][2], acc[mi][ni][3]);
        }
    }
}

// ------------- RMSNorm + RoPE + transpose -> [b,h,t,d] fp16 -------------------
__global__ __launch_bounds__(128) void norm_rope_kernel(
    const float* __restrict__ src, __half* __restrict__ dst,
    const float* __restrict__ w, int nheads, int srcStride)
{
    int r = blockIdx.x;              // (b*T+t)*nheads + h
    int d = threadIdx.x;             // 0..127
    int h  = r % nheads;
    int bt = r / nheads;
    int t  = bt % TT;
    int b  = bt / TT;

    float val = src[(size_t)bt * srcStride + h * HD + d];
    __shared__ float red[4];
    __shared__ float sh[HD];

    float ss = val * val;
    #pragma unroll
    for (int off = 16; off; off >>= 1)
        ss += __shfl_xor_sync(0xffffffffu, ss, off);
    if ((d & 31) == 0) red[d >> 5] = ss;
    __syncthreads();
    float tot = red[0] + red[1] + red[2] + red[3];
    float nv = val * rsqrtf(tot * (1.0f / HD) + 1e-6f) * w[d];
    sh[d] = nv;
    __syncthreads();

    int j = d & 63;
    float c = g_cos[t * 64 + j];
    float s = g_sin[t * 64 + j];
    float other = (d < 64) ? -sh[d + 64] : sh[d - 64];
    float out = nv * c + other * s;

    dst[((size_t)(b * nheads + h) * TT + t) * HD + d] = __float2half(out);
}

// ------------- V transpose -> [b,h,t,d] fp16 ----------------------------------
__global__ __launch_bounds__(128) void transpose_kernel(
    const float* __restrict__ src, __half* __restrict__ dst, int nheads, int srcStride)
{
    int r = blockIdx.x;
    int d = threadIdx.x;
    int h  = r % nheads;
    int bt = r / nheads;
    int t  = bt % TT;
    int b  = bt / TT;
    dst[((size_t)(b * nheads + h) * TT + t) * HD + d] =
        __float2half(src[(size_t)bt * srcStride + h * HD + d]);
}

// ------------- Causal flash attention, fp16 mma + ldmatrix, 2 heads/CTA -------
#define US_STR 136   // halves; 272B rows -> ldmatrix conflict-free
#define PS_STR 72
#define FL_KV  (64 * US_STR)
#define FL_U   (128 * US_STR)
#define FLASH_SMEM ((2 * FL_KV + FL_U) * 2)

__global__ __launch_bounds__(256) void flash_fp16_kernel(
    const __half* __restrict__ Q, const __half* __restrict__ Kt,
    const __half* __restrict__ Vt, __half* __restrict__ ctx)
{
    extern __shared__ __half smh[];
    __half* Ks = smh;
    __half* Vs = smh + FL_KV;
    __half* Us = smh + 2 * FL_KV;
    __half* Ps = Us;

    int tid = threadIdx.x;
    int wid = tid >> 5, lane = tid & 31;
    int g = lane >> 2, tg = lane & 3;
    int lr = lane & 7;
    int lm = (lane >> 3) & 1;
    int lh = lane >> 4;

    int hw = wid >> 2;
    int w4 = wid & 3;
    int base = w4 * 16;

    int qb = blockIdx.x;
    int bk = blockIdx.y;
    int b = bk / NKV, kvh = bk % NKV;
    int h = kvh * 2 + hw;

    const __half* Kbase = Kt + ((size_t)(b * NKV + kvh) * TT) * HD;
    const __half* Vbase = Vt + ((size_t)(b * NKV + kvh) * TT) * HD;

    uint32_t sK = smem_u32(Ks), sV = smem_u32(Vs), sU = smem_u32(Us), sP = sU;

    {
        const __half* Qh = Q + ((size_t)(b * NH + kvh * 2 + hw) * TT + qb * 64) * HD;
        int t128 = tid & 127;
        #pragma unroll
        for (int it = 0; it < 8; ++it) {
            int idx = it * 128 + t128;
            int r = idx >> 4;
            int c8 = (idx & 15) * 8;
            *(int4*)&Us[(hw * 64 + r) * US_STR + c8] =
                *(const int4*)(Qh + (size_t)r * HD + c8);
        }
    }
    __syncthreads();

    uint32_t qa[8][4];
    #pragma unroll
    for (int ks = 0; ks < 8; ++ks) {
        uint32_t au = sU + (uint32_t)(((hw * 64 + base + lr + lm * 8) * US_STR + ks * 16 + lh * 8) * 2);
        LDSM_X4(qa[ks][0], qa[ks][1], qa[ks][2], qa[ks][3], au);
    }

    float o[16][4];
    #pragma unroll
    for (int ni = 0; ni < 16; ni++)
        #pragma unroll
        for (int c = 0; c < 4; c++) o[ni][c] = 0.f;
    float mrow[2] = {-1e30f, -1e30f};
    float lrow[2] = {0.f, 0.f};

    const float scale = 0.08838834764831845f;   // 128^-0.5
    const float L2E = 1.44269504088896f;

    for (int kb = 0; kb <= qb; ++kb) {
        const __half* Kp = Kbase + (size_t)kb * 64 * HD;
        const __half* Vp = Vbase + (size_t)kb * 64 * HD;
        __syncthreads();
        #pragma unroll
        for (int it = 0; it < 4; ++it) {
            int idx = it * 256 + tid;
            int r = idx >> 4;
            int c8 = (idx & 15) * 8;
            *(int4*)&Ks[r * US_STR + c8] = *(const int4*)(Kp + (size_t)r * HD + c8);
            *(int4*)&Vs[r * US_STR + c8] = *(const int4*)(Vp + (size_t)r * HD + c8);
        }
        __syncthreads();

        float s[8][4];
        #pragma unroll
        for (int ni = 0; ni < 8; ni++)
            #pragma unroll
            for (int c = 0; c < 4; c++) s[ni][c] = 0.f;

        #pragma unroll
        for (int ks = 0; ks < 8; ++ks) {
            int kk = ks * 16;
            #pragma unroll
            for (int ni = 0; ni < 8; ni++) {
                uint32_t b0, b1;
                uint32_t ak = sK + (uint32_t)(((ni * 8 + lr) * US_STR + kk + lm * 8) * 2);
                LDSM_X2(b0, b1, ak);
                mma_f16(s[ni], qa[ks], b0, b1);
            }
        }

        bool diag = (kb == qb);
        int rowA = base + g;
        int rowB = rowA + 8;
        float mA = -1e30f, mB = -1e30f;
        #pragma unroll
        for (int ni = 0; ni < 8; ni++) {
            #pragma unroll
            for (int c = 0; c < 4; c++) {
                float sv = s[ni][c] * scale;
                if (diag) {
                    int kcol = ni * 8 + tg * 2 + (c & 1);
                    int qrow = (c < 2) ? rowA : rowB;
                    if (kcol > qrow) sv = -1e30f;
                }
                s[ni][c] = sv;
            }
            mA = fmaxf(mA, fmaxf(s[ni][0], s[ni][1]));
            mB = fmaxf(mB, fmaxf(s[ni][2], s[ni][3]));
        }
        #pragma unroll
        for (int off = 1; off < 4; off <<= 1) {
            mA = fmaxf(mA, __shfl_xor_sync(0xffffffffu, mA, off));
            mB = fmaxf(mB, __shfl_xor_sync(0xffffffffu, mB, off));
        }
        float mnA = fmaxf(mrow[0], mA);
        float mnB = fmaxf(mrow[1], mB);
        float alA = exp2f((mrow[0] - mnA) * L2E);
        float alB = exp2f((mrow[1] - mnB) * L2E);
        mrow[0] = mnA; mrow[1] = mnB;

        float lA = 0.f, lB = 0.f;
        #pragma unroll
        for (int ni = 0; ni < 8; ni++) {
            s[ni][0] = exp2f((s[ni][0] - mnA) * L2E);
            s[ni][1] = exp2f((s[ni][1] - mnA) * L2E);
            s[ni][2] = exp2f((s[ni][2] - mnB) * L2E);
            s[ni][3] = exp2f((s[ni][3] - mnB) * L2E);
            lA += s[ni][0] + s[ni][1];
            lB += s[ni][2] + s[ni][3];
        }
        #pragma unroll
        for (int off = 1; off < 4; off <<= 1) {
            lA += __shfl_xor_sync(0xffffffffu, lA, off);
            lB += __shfl_xor_sync(0xffffffffu, lB, off);
        }
        lrow[0] = lrow[0] * alA + lA;
        lrow[1] = lrow[1] * alB + lB;
        #pragma unroll
        for (int ni = 0; ni < 16; ni++) {
            o[ni][0] *= alA; o[ni][1] *= alA;
            o[ni][2] *= alB; o[ni][3] *= alB;
        }

        int prowA = hw * 64 + rowA;
        int prowB = hw * 64 + rowB;
        #pragma unroll
        for (int ni = 0; ni < 8; ni++) {
            int cn = ni * 8 + tg * 2;
            *(__half2*)&Ps[prowA * PS_STR + cn] = __floats2half2_rn(s[ni][0], s[ni][1]);
            *(__half2*)&Ps[prowB * PS_STR + cn] = __floats2half2_rn(s[ni][2], s[ni][3]);
        }
        __syncwarp();

        #pragma unroll
        for (int ks = 0; ks < 4; ++ks) {
            int kk = ks * 16;
            uint32_t pa4[4];
            uint32_t ap = sP + (uint32_t)(((hw * 64 + base + lr + lm * 8) * PS_STR + kk + lh * 8) * 2);
            LDSM_X4(pa4[0], pa4[1], pa4[2], pa4[3], ap);
            #pragma unroll
            for (int ni = 0; ni < 16; ni++) {
                uint32_t b0, b1;
                uint32_t av = sV + (uint32_t)(((kk + lr + lm * 8) * US_STR + ni * 8) * 2);
                LDSM_X2T(b0, b1, av);
                mma_f16(o[ni], pa4, b0, b1);
            }
        }
    }

    float ivA = 1.0f / lrow[0];
    float ivB = 1.0f / lrow[1];
    int qA = qb * 64 + base + g;
    int qB = qA + 8;
    size_t offA = (size_t)(b * TT + qA) * (NH * HD) + h * HD;
    size_t offB = (size_t)(b * TT + qB) * (NH * HD) + h * HD;
    #pragma unroll
    for (int ni = 0; ni < 16; ni++) {
        int dn = ni * 8 + tg * 2;
        *(__half2*)(ctx + offA + dn) = __floats2half2_rn(o[ni][0] * ivA, o[ni][1] * ivA);
        *(__half2*)(ctx + offB + dn) = __floats2half2_rn(o[ni][2] * ivB, o[ni][3] * ivB);
    }
}

// ---------------------------- launch -----------------------------------------
extern "C" void kernel_launch(void* const* d_in, const int* in_sizes, int n_in,
                              void* d_out, int out_size)
{
    const float* x    = (const float*)d_in[0];
    // d_in[1] = attn_mask (pure causal; applied analytically)
    const float* Wq   = (const float*)d_in[2];
    const float* Wk   = (const float*)d_in[3];
    const float* Wv   = (const float*)d_in[4];
    const float* Wo   = (const float*)d_in[5];
    const float* qnw  = (const float*)d_in[6];
    const float* knw  = (const float*)d_in[7];
    float* out = (float*)d_out;

    float *qkvraw;
    __half *qt, *kt, *vt, *xh, *wqkv, *wo, *ctx;
    cudaGetSymbolAddress((void**)&qkvraw, g_qkvraw);
    cudaGetSymbolAddress((void**)&qt,   g_qt);
    cudaGetSymbolAddress((void**)&kt,   g_kt);
    cudaGetSymbolAddress((void**)&vt,   g_vt);
    cudaGetSymbolAddress((void**)&xh,   g_xh);
    cudaGetSymbolAddress((void**)&wqkv, g_wqkv);
    cudaGetSymbolAddress((void**)&wo,   g_wo);
    cudaGetSymbolAddress((void**)&ctx,  g_ctx);

    cudaFuncSetAttribute(flash_fp16_kernel, cudaFuncAttributeMaxDynamicSharedMemorySize,
                         FLASH_SMEM);

    // 0: rope table
    rope_table_kernel<<<TT, 64>>>();
    // 1: x -> fp16
    conv_half_kernel<<<(unsigned)(((size_t)MM * HH / 4 + 255) / 256), 256>>>(
        x, xh, (size_t)MM * HH);
    // 2-4: W^T fp16 (QKV into one buffer)
    wt_half_kernel<<<dim3(2048 / 32, 2048 / 32), 256>>>(Wq, wqkv, 2048, 2048);
    wt_half_kernel<<<dim3(1024 / 32, 2048 / 32), 256>>>(Wk, wqkv + (size_t)2048 * 2048, 2048, 1024);
    wt_half_kernel<<<dim3(1024 / 32, 2048 / 32), 256>>>(Wv, wqkv + (size_t)3072 * 2048, 2048, 1024);
    // 5: fused QKV projection (N=4096)  [ncu capture slot]
    gemm_fp16_kernel<<<dim3(4096 / 128, MM / 128), 256>>>(xh, wqkv, qkvraw, MM, 4096, HH);
    // 6-8: RMSNorm/RoPE/transpose -> fp16
    norm_rope_kernel<<<BB * TT * NH, 128>>>(qkvraw, qt, qnw, NH, 4096);
    norm_rope_kernel<<<BB * TT * NKV, 128>>>(qkvraw + 2048, kt, knw, NKV, 4096);
    transpose_kernel<<<BB * TT * NKV, 128>>>(qkvraw + 3072, vt, NKV, 4096);
    // 9: Wo^T fp16
    wt_half_kernel<<<dim3(2048 / 32, 2048 / 32), 256>>>(Wo, wo, 2048, 2048);
    // 10: flash attention (fp16 mma, 2 GQA heads/CTA)
    flash_fp16_kernel<<<dim3(TT / 64, BB * NKV), 256, FLASH_SMEM>>>(qt, kt, vt, ctx);
    // 11: output projection
    gemm_fp16_kernel<<<dim3(2048 / 128, MM / 128), 256>>>(ctx, wo, out, MM, 2048, HH);
}

// round 8
// speedup vs baseline: 6.2005x; 1.0490x over previous
#include <cuda_runtime.h>
#include <cuda_fp16.h>
#include <cstdint>
#include <cstddef>
#include <math.h>

// Problem constants
#define BB   2
#define TT   2048
#define HH   2048
#define NH   16
#define NKV  8
#define HD   128
#define MM   (BB*TT)            // 4096 rows

// ---------------- scratch (static device globals; no allocation) -------------
__device__ float g_qkvraw[(size_t)MM * 4096];      // [b*T+t, {Q|K|V}]
__device__ __half g_qt[(size_t)BB * NH * TT * HD]; // [b,h,t,d] fp16
__device__ __half g_kt[(size_t)BB * NKV * TT * HD];
__device__ __half g_vt[(size_t)BB * NKV * TT * HD];
__device__ __half g_xh[(size_t)MM * HH];           // x fp16
__device__ __half g_wqkv[(size_t)4096 * 2048];     // [N=4096, K=2048] fp16 (Q|K|V rows)
__device__ __half g_wo[(size_t)2048 * 2048];       // Wo^T [N,K] fp16
__device__ __half g_ctx[(size_t)MM * HH];          // [b*T+t, h*HD+d] fp16
__device__ float g_cos[TT * 64];
__device__ float g_sin[TT * 64];

// ---------------- helpers ----------------------------------------------------
__device__ __forceinline__ uint32_t smem_u32(const void* p) {
    uint32_t a;
    asm("{ .reg .u64 t; cvta.to.shared.u64 t, %1; cvt.u32.u64 %0, t; }" : "=r"(a) : "l"(p));
    return a;
}

__device__ __forceinline__ void mma_f16(float c[4], const uint32_t a[4],
                                        uint32_t b0, uint32_t b1) {
    asm volatile(
        "mma.sync.aligned.m16n8k16.row.col.f32.f16.f16.f32 "
        "{%0,%1,%2,%3}, {%4,%5,%6,%7}, {%8,%9}, {%0,%1,%2,%3};\n"
        : "+f"(c[0]), "+f"(c[1]), "+f"(c[2]), "+f"(c[3])
        : "r"(a[0]), "r"(a[1]), "r"(a[2]), "r"(a[3]), "r"(b0), "r"(b1));
}

#define LDSM_X4(R0,R1,R2,R3,ADDR)                                              \
    asm volatile("ldmatrix.sync.aligned.m8n8.x4.shared.b16 {%0,%1,%2,%3}, [%4];" \
        : "=r"(R0), "=r"(R1), "=r"(R2), "=r"(R3) : "r"(ADDR))
#define LDSM_X4T(R0,R1,R2,R3,ADDR)                                             \
    asm volatile("ldmatrix.sync.aligned.m8n8.x4.trans.shared.b16 {%0,%1,%2,%3}, [%4];" \
        : "=r"(R0), "=r"(R1), "=r"(R2), "=r"(R3) : "r"(ADDR))

// ---------------- RoPE tables (fp64 angle, fp32 trig after reduction) ---------
__global__ void rope_table_kernel() {
    int t = blockIdx.x * 2 + (threadIdx.x >> 6);
    int j = threadIdx.x & 63;  // 0..63
    double inv = exp(-(double)j * (13.815510557964274 / 64.0)); // theta=1e6
    double ang = (double)t * inv;
    // range-reduce in fp64, then fp32 sincos (error ~1e-7)
    const double TWO_PI = 6.283185307179586476925286766559;
    double red = ang - TWO_PI * floor(ang * (1.0 / TWO_PI));
    float c, s;
    __sincosf(0.0f, &s, &c);  // dummy to keep fast path linked (overwritten)
    sincosf((float)red, &s, &c);
    g_cos[t * 64 + j] = c;
    g_sin[t * 64 + j] = s;
}

// ---------------- fp32 -> fp16 convert ----------------------------------------
__global__ __launch_bounds__(256) void conv_half_kernel(
    const float* __restrict__ in, __half* __restrict__ out, size_t n)
{
    size_t i = ((size_t)blockIdx.x * 256 + threadIdx.x) * 4;
    if (i < n) {
        float4 v = *(const float4*)(in + i);
        *(__half2*)(out + i)     = __floats2half2_rn(v.x, v.y);
        *(__half2*)(out + i + 2) = __floats2half2_rn(v.z, v.w);
    }
}

// ---------------- W [K,N] fp32 -> Wt [N,K] fp16 -------------------------------
__global__ __launch_bounds__(256) void wt_half_kernel(
    const float* __restrict__ W, __half* __restrict__ Wt, int K, int N_)
{
    __shared__ float t[32][33];
    int n0 = blockIdx.x * 32, k0 = blockIdx.y * 32;
    int tx = threadIdx.x & 31, ty = threadIdx.x >> 5;   // 32 x 8
    #pragma unroll
    for (int i = 0; i < 32; i += 8)
        t[ty + i][tx] = W[(size_t)(k0 + ty + i) * N_ + n0 + tx];
    __syncthreads();
    #pragma unroll
    for (int i = 0; i < 32; i += 8)
        Wt[(size_t)(n0 + ty + i) * K + k0 + tx] = __float2half(t[tx][ty + i]);
}

// ---------------- fp16 tensor-core GEMM: C[M,N] = A[M,K] @ B[N,K]^T -----------
// BK=32, double-buffered smem, ldmatrix fragment loads.
#define GAS 40   // smem row stride in halves (80B = 5x16B, odd -> ldmatrix clean)
#define GSTG (128 * GAS)
__global__ __launch_bounds__(256, 2) void gemm_fp16_kernel(
    const __half* __restrict__ A, const __half* __restrict__ Bm,
    float* __restrict__ C, int M, int N_, int K)
{
    __shared__ __half As[2 * GSTG];
    __shared__ __half Bs[2 * GSTG];

    int tid = threadIdx.x;
    int wid = tid >> 5, lane = tid & 31;
    int g = lane >> 2, tg = lane & 3;
    int lr = lane & 7;
    int lm = (lane >> 3) & 1;
    int lh = lane >> 4;
    int sel = lane >> 3;
    int warpRow = wid >> 1, warpCol = wid & 1;  // 4 x 2 warps
    int brow = blockIdx.y * 128, bcol = blockIdx.x * 128;

    int rowL[2], segL[2];
    #pragma unroll
    for (int it = 0; it < 2; ++it) {
        int idx = it * 256 + tid;
        rowL[it] = idx >> 2;
        segL[it] = (idx & 3) * 8;
    }
    const __half* ApL[2];
    const __half* BpL[2];
    #pragma unroll
    for (int it = 0; it < 2; ++it) {
        ApL[it] = A  + (size_t)(brow + rowL[it]) * K + segL[it];
        BpL[it] = Bm + (size_t)(bcol + rowL[it]) * K + segL[it];
    }

    uint32_t sA = smem_u32(As), sB = smem_u32(Bs);

    float acc[2][8][4];
    #pragma unroll
    for (int mi = 0; mi < 2; mi++)
        #pragma unroll
        for (int ni = 0; ni < 8; ni++)
            #pragma unroll
            for (int c = 0; c < 4; c++) acc[mi][ni][c] = 0.f;

    #pragma unroll
    for (int it = 0; it < 2; ++it) {
        *(int4*)&As[rowL[it] * GAS + segL[it]] = *(const int4*)ApL[it];
        *(int4*)&Bs[rowL[it] * GAS + segL[it]] = *(const int4*)BpL[it];
    }
    __syncthreads();

    int buf = 0;
    for (int k0 = 0; k0 < K; k0 += 32) {
        int4 pa[2], pb[2];
        bool more = (k0 + 32 < K);
        if (more) {
            #pragma unroll
            for (int it = 0; it < 2; ++it) {
                pa[it] = *(const int4*)(ApL[it] + k0 + 32);
                pb[it] = *(const int4*)(BpL[it] + k0 + 32);
            }
        }

        uint32_t bA = sA + buf * (GSTG * 2);
        uint32_t bB = sB + buf * (GSTG * 2);
        #pragma unroll
        for (int ks = 0; ks < 2; ++ks) {
            int kk = ks * 16;
            uint32_t af[2][4];
            #pragma unroll
            for (int mi = 0; mi < 2; mi++) {
                uint32_t addr = bA + (uint32_t)(((warpRow * 32 + mi * 16 + lr + lm * 8) * GAS
                                                 + kk + lh * 8) * 2);
                LDSM_X4(af[mi][0], af[mi][1], af[mi][2], af[mi][3], addr);
            }
            uint32_t bf[8][2];
            #pragma unroll
            for (int nb = 0; nb < 4; nb++) {
                int n0 = warpCol * 64 + nb * 16;
                uint32_t addr = bB + (uint32_t)(((n0 + lr + (sel >> 1) * 8) * GAS
                                                 + kk + (sel & 1) * 8) * 2);
                LDSM_X4(bf[2 * nb][0], bf[2 * nb][1], bf[2 * nb + 1][0], bf[2 * nb + 1][1], addr);
            }
            #pragma unroll
            for (int mi = 0; mi < 2; mi++)
                #pragma unroll
                for (int ni = 0; ni < 8; ni++)
                    mma_f16(acc[mi][ni], af[mi], bf[ni][0], bf[ni][1]);
        }

        if (more) {
            __half* Ad = As + (buf ^ 1) * GSTG;
            __half* Bd = Bs + (buf ^ 1) * GSTG;
            #pragma unroll
            for (int it = 0; it < 2; ++it) {
                *(int4*)&Ad[rowL[it] * GAS + segL[it]] = pa[it];
                *(int4*)&Bd[rowL[it] * GAS + segL[it]] = pb[it];
            }
        }
        __syncthreads();
        buf ^= 1;
    }

    #pragma unroll
    for (int mi = 0; mi < 2; mi++) {
        int r0 = brow + warpRow * 32 + mi * 16 + g;
        #pragma unroll
        for (int ni = 0; ni < 8; ni++) {
            int cn = bcol + warpCol * 64 + ni * 8 + tg * 2;
            *(float2*)(C + (size_t)r0 * N_ + cn) = make_float2(acc[mi][ni][0], acc[mi][ni][1]);
            *(float2*)(C + (size_t)(r0 + 8) * N_ + cn) = make_float2(acc[mi][ni][2], acc[mi][ni][3]);
        }
    }
}

// ------------- RMSNorm + RoPE + transpose -> [b,h,t,d] fp16 -------------------
__global__ __launch_bounds__(128) void norm_rope_kernel(
    const float* __restrict__ src, __half* __restrict__ dst,
    const float* __restrict__ w, int nheads, int srcStride)
{
    int r = blockIdx.x;              // (b*T+t)*nheads + h
    int d = threadIdx.x;             // 0..127
    int h  = r % nheads;
    int bt = r / nheads;
    int t  = bt % TT;
    int b  = bt / TT;

    float val = src[(size_t)bt * srcStride + h * HD + d];
    __shared__ float red[4];
    __shared__ float sh[HD];

    float ss = val * val;
    #pragma unroll
    for (int off = 16; off; off >>= 1)
        ss += __shfl_xor_sync(0xffffffffu, ss, off);
    if ((d & 31) == 0) red[d >> 5] = ss;
    __syncthreads();
    float tot = red[0] + red[1] + red[2] + red[3];
    float nv = val * rsqrtf(tot * (1.0f / HD) + 1e-6f) * w[d];
    sh[d] = nv;
    __syncthreads();

    int j = d & 63;
    float c = g_cos[t * 64 + j];
    float s = g_sin[t * 64 + j];
    float other = (d < 64) ? -sh[d + 64] : sh[d - 64];
    float out = nv * c + other * s;

    dst[((size_t)(b * nheads + h) * TT + t) * HD + d] = __float2half(out);
}

// ------------- V transpose -> [b,h,t,d] fp16 ----------------------------------
__global__ __launch_bounds__(128) void transpose_kernel(
    const float* __restrict__ src, __half* __restrict__ dst, int nheads, int srcStride)
{
    int r = blockIdx.x;
    int d = threadIdx.x;
    int h  = r % nheads;
    int bt = r / nheads;
    int t  = bt % TT;
    int b  = bt / TT;
    dst[((size_t)(b * nheads + h) * TT + t) * HD + d] =
        __float2half(src[(size_t)bt * srcStride + h * HD + d]);
}

// ------------- Causal flash attention, fp16 mma + ldmatrix.x4, 2 heads/CTA ----
#define US_STR 136   // halves; 272B rows -> ldmatrix conflict-free
#define PS_STR 72
#define FL_KV  (64 * US_STR)
#define FL_U   (128 * US_STR)
#define FLASH_SMEM ((2 * FL_KV + FL_U) * 2)

__global__ __launch_bounds__(256) void flash_fp16_kernel(
    const __half* __restrict__ Q, const __half* __restrict__ Kt,
    const __half* __restrict__ Vt, __half* __restrict__ ctx)
{
    extern __shared__ __half smh[];
    __half* Ks = smh;
    __half* Vs = smh + FL_KV;
    __half* Us = smh + 2 * FL_KV;
    __half* Ps = Us;

    int tid = threadIdx.x;
    int wid = tid >> 5, lane = tid & 31;
    int g = lane >> 2, tg = lane & 3;
    int lr = lane & 7;
    int lm = (lane >> 3) & 1;     // 8-group parity
    int lh = lane >> 4;           // 16-group
    int p8 = (lane >> 3) & 1;     // pair selectors for x4 B loads
    int p16 = lane >> 4;

    int hw = wid >> 2;
    int w4 = wid & 3;
    int base = w4 * 16;

    int qb = blockIdx.x;
    int bk = blockIdx.y;
    int b = bk / NKV, kvh = bk % NKV;
    int h = kvh * 2 + hw;

    const __half* Kbase = Kt + ((size_t)(b * NKV + kvh) * TT) * HD;
    const __half* Vbase = Vt + ((size_t)(b * NKV + kvh) * TT) * HD;

    uint32_t sK = smem_u32(Ks), sV = smem_u32(Vs), sU = smem_u32(Us), sP = sU;

    {
        const __half* Qh = Q + ((size_t)(b * NH + kvh * 2 + hw) * TT + qb * 64) * HD;
        int t128 = tid & 127;
        #pragma unroll
        for (int it = 0; it < 8; ++it) {
            int idx = it * 128 + t128;
            int r = idx >> 4;
            int c8 = (idx & 15) * 8;
            *(int4*)&Us[(hw * 64 + r) * US_STR + c8] =
                *(const int4*)(Qh + (size_t)r * HD + c8);
        }
    }
    __syncthreads();

    uint32_t qa[8][4];
    #pragma unroll
    for (int ks = 0; ks < 8; ++ks) {
        uint32_t au = sU + (uint32_t)(((hw * 64 + base + lr + lm * 8) * US_STR + ks * 16 + lh * 8) * 2);
        LDSM_X4(qa[ks][0], qa[ks][1], qa[ks][2], qa[ks][3], au);
    }

    float o[16][4];
    #pragma unroll
    for (int ni = 0; ni < 16; ni++)
        #pragma unroll
        for (int c = 0; c < 4; c++) o[ni][c] = 0.f;
    float mrow[2] = {-1e30f, -1e30f};
    float lrow[2] = {0.f, 0.f};

    const float scale = 0.08838834764831845f;   // 128^-0.5
    const float L2E = 1.44269504088896f;

    for (int kb = 0; kb <= qb; ++kb) {
        const __half* Kp = Kbase + (size_t)kb * 64 * HD;
        const __half* Vp = Vbase + (size_t)kb * 64 * HD;
        __syncthreads();
        #pragma unroll
        for (int it = 0; it < 4; ++it) {
            int idx = it * 256 + tid;
            int r = idx >> 4;
            int c8 = (idx & 15) * 8;
            *(int4*)&Ks[r * US_STR + c8] = *(const int4*)(Kp + (size_t)r * HD + c8);
            *(int4*)&Vs[r * US_STR + c8] = *(const int4*)(Vp + (size_t)r * HD + c8);
        }
        __syncthreads();

        // ---- S = Q @ K^T (x4 pair loads) ------------------------------------
        float s[8][4];
        #pragma unroll
        for (int ni = 0; ni < 8; ni++)
            #pragma unroll
            for (int c = 0; c < 4; c++) s[ni][c] = 0.f;

        #pragma unroll
        for (int ks = 0; ks < 8; ++ks) {
            int kk = ks * 16;
            #pragma unroll
            for (int np = 0; np < 4; np++) {
                uint32_t r0, r1, r2, r3;
                uint32_t ak = sK + (uint32_t)(((np * 16 + p16 * 8 + lr) * US_STR
                                               + kk + p8 * 8) * 2);
                LDSM_X4(r0, r1, r2, r3, ak);
                mma_f16(s[2 * np],     qa[ks], r0, r1);
                mma_f16(s[2 * np + 1], qa[ks], r2, r3);
            }
        }

        // ---- online softmax --------------------------------------------------
        bool diag = (kb == qb);
        int rowA = base + g;
        int rowB = rowA + 8;
        float mA = -1e30f, mB = -1e30f;
        #pragma unroll
        for (int ni = 0; ni < 8; ni++) {
            #pragma unroll
            for (int c = 0; c < 4; c++) {
                float sv = s[ni][c] * scale;
                if (diag) {
                    int kcol = ni * 8 + tg * 2 + (c & 1);
                    int qrow = (c < 2) ? rowA : rowB;
                    if (kcol > qrow) sv = -1e30f;
                }
                s[ni][c] = sv;
            }
            mA = fmaxf(mA, fmaxf(s[ni][0], s[ni][1]));
            mB = fmaxf(mB, fmaxf(s[ni][2], s[ni][3]));
        }
        #pragma unroll
        for (int off = 1; off < 4; off <<= 1) {
            mA = fmaxf(mA, __shfl_xor_sync(0xffffffffu, mA, off));
            mB = fmaxf(mB, __shfl_xor_sync(0xffffffffu, mB, off));
        }
        float mnA = fmaxf(mrow[0], mA);
        float mnB = fmaxf(mrow[1], mB);
        float alA = exp2f((mrow[0] - mnA) * L2E);
        float alB = exp2f((mrow[1] - mnB) * L2E);
        mrow[0] = mnA; mrow[1] = mnB;

        float lA = 0.f, lB = 0.f;
        #pragma unroll
        for (int ni = 0; ni < 8; ni++) {
            s[ni][0] = exp2f((s[ni][0] - mnA) * L2E);
            s[ni][1] = exp2f((s[ni][1] - mnA) * L2E);
            s[ni][2] = exp2f((s[ni][2] - mnB) * L2E);
            s[ni][3] = exp2f((s[ni][3] - mnB) * L2E);
            lA += s[ni][0] + s[ni][1];
            lB += s[ni][2] + s[ni][3];
        }
        #pragma unroll
        for (int off = 1; off < 4; off <<= 1) {
            lA += __shfl_xor_sync(0xffffffffu, lA, off);
            lB += __shfl_xor_sync(0xffffffffu, lB, off);
        }
        lrow[0] = lrow[0] * alA + lA;
        lrow[1] = lrow[1] * alB + lB;
        #pragma unroll
        for (int ni = 0; ni < 16; ni++) {
            o[ni][0] *= alA; o[ni][1] *= alA;
            o[ni][2] *= alB; o[ni][3] *= alB;
        }

        int prowA = hw * 64 + rowA;
        int prowB = hw * 64 + rowB;
        #pragma unroll
        for (int ni = 0; ni < 8; ni++) {
            int cn = ni * 8 + tg * 2;
            *(__half2*)&Ps[prowA * PS_STR + cn] = __floats2half2_rn(s[ni][0], s[ni][1]);
            *(__half2*)&Ps[prowB * PS_STR + cn] = __floats2half2_rn(s[ni][2], s[ni][3]);
        }
        __syncwarp();

        // ---- O += P @ V (x4.trans pair loads) --------------------------------
        #pragma unroll
        for (int ks = 0; ks < 4; ++ks) {
            int kk = ks * 16;
            uint32_t pa4[4];
            uint32_t ap = sP + (uint32_t)(((hw * 64 + base + lr + lm * 8) * PS_STR + kk + lh * 8) * 2);
            LDSM_X4(pa4[0], pa4[1], pa4[2], pa4[3], ap);
            #pragma unroll
            for (int np = 0; np < 8; np++) {
                uint32_t r0, r1, r2, r3;
                uint32_t av = sV + (uint32_t)(((kk + p8 * 8 + lr) * US_STR
                                               + np * 16 + p16 * 8) * 2);
                LDSM_X4T(r0, r1, r2, r3, av);
                mma_f16(o[2 * np],     pa4, r0, r1);
                mma_f16(o[2 * np + 1], pa4, r2, r3);
            }
        }
    }

    float ivA = 1.0f / lrow[0];
    float ivB = 1.0f / lrow[1];
    int qA = qb * 64 + base + g;
    int qB = qA + 8;
    size_t offA = (size_t)(b * TT + qA) * (NH * HD) + h * HD;
    size_t offB = (size_t)(b * TT + qB) * (NH * HD) + h * HD;
    #pragma unroll
    for (int ni = 0; ni < 16; ni++) {
        int dn = ni * 8 + tg * 2;
        *(__half2*)(ctx + offA + dn) = __floats2half2_rn(o[ni][0] * ivA, o[ni][1] * ivA);
        *(__half2*)(ctx + offB + dn) = __floats2half2_rn(o[ni][2] * ivB, o[ni][3] * ivB);
    }
}

// ---------------------------- launch -----------------------------------------
extern "C" void kernel_launch(void* const* d_in, const int* in_sizes, int n_in,
                              void* d_out, int out_size)
{
    const float* x    = (const float*)d_in[0];
    // d_in[1] = attn_mask (pure causal; applied analytically)
    const float* Wq   = (const float*)d_in[2];
    const float* Wk   = (const float*)d_in[3];
    const float* Wv   = (const float*)d_in[4];
    const float* Wo   = (const float*)d_in[5];
    const float* qnw  = (const float*)d_in[6];
    const float* knw  = (const float*)d_in[7];
    float* out = (float*)d_out;

    float *qkvraw;
    __half *qt, *kt, *vt, *xh, *wqkv, *wo, *ctx;
    cudaGetSymbolAddress((void**)&qkvraw, g_qkvraw);
    cudaGetSymbolAddress((void**)&qt,   g_qt);
    cudaGetSymbolAddress((void**)&kt,   g_kt);
    cudaGetSymbolAddress((void**)&vt,   g_vt);
    cudaGetSymbolAddress((void**)&xh,   g_xh);
    cudaGetSymbolAddress((void**)&wqkv, g_wqkv);
    cudaGetSymbolAddress((void**)&wo,   g_wo);
    cudaGetSymbolAddress((void**)&ctx,  g_ctx);

    cudaFuncSetAttribute(flash_fp16_kernel, cudaFuncAttributeMaxDynamicSharedMemorySize,
                         FLASH_SMEM);

    // 0: rope table
    rope_table_kernel<<<TT / 2, 128>>>();
    // 1: x -> fp16
    conv_half_kernel<<<(unsigned)(((size_t)MM * HH / 4 + 255) / 256), 256>>>(
        x, xh, (size_t)MM * HH);
    // 2-4: W^T fp16 (QKV into one buffer)
    wt_half_kernel<<<dim3(2048 / 32, 2048 / 32), 256>>>(Wq, wqkv, 2048, 2048);
    wt_half_kernel<<<dim3(1024 / 32, 2048 / 32), 256>>>(Wk, wqkv + (size_t)2048 * 2048, 2048, 1024);
    wt_half_kernel<<<dim3(1024 / 32, 2048 / 32), 256>>>(Wv, wqkv + (size_t)3072 * 2048, 2048, 1024);
    // 5: fused QKV projection (N=4096)  [ncu capture slot]
    gemm_fp16_kernel<<<dim3(4096 / 128, MM / 128), 256>>>(xh, wqkv, qkvraw, MM, 4096, HH);
    // 6-8: RMSNorm/RoPE/transpose -> fp16
    norm_rope_kernel<<<BB * TT * NH, 128>>>(qkvraw, qt, qnw, NH, 4096);
    norm_rope_kernel<<<BB * TT * NKV, 128>>>(qkvraw + 2048, kt, knw, NKV, 4096);
    transpose_kernel<<<BB * TT * NKV, 128>>>(qkvraw + 3072, vt, NKV, 4096);
    // 9: Wo^T fp16
    wt_half_kernel<<<dim3(2048 / 32, 2048 / 32), 256>>>(Wo, wo, 2048, 2048);
    // 10: flash attention (fp16 mma, 2 GQA heads/CTA)
    flash_fp16_kernel<<<dim3(TT / 64, BB * NKV), 256, FLASH_SMEM>>>(qt, kt, vt, ctx);
    // 11: output projection
    gemm_fp16_kernel<<<dim3(2048 / 128, MM / 128), 256>>>(ctx, wo, out, MM, 2048, HH);
}

// round 9
// speedup vs baseline: 6.5313x; 1.0533x over previous
#include <cuda_runtime.h>
#include <cuda_fp16.h>
#include <cstdint>
#include <cstddef>
#include <math.h>

// Problem constants
#define BB   2
#define TT   2048
#define HH   2048
#define NH   16
#define NKV  8
#define HD   128
#define MM   (BB*TT)            // 4096 rows

// ---------------- scratch (static device globals; no allocation) -------------
__device__ float g_qkvraw[(size_t)MM * 4096];      // [b*T+t, {Q|K|V}]
__device__ __half g_qt[(size_t)BB * NH * TT * HD]; // [b,h,t,d] fp16
__device__ __half g_kt[(size_t)BB * NKV * TT * HD];
__device__ __half g_vt[(size_t)BB * NKV * TT * HD];
__device__ __half g_xh[(size_t)MM * HH];           // x fp16
__device__ __half g_wqkv[(size_t)4096 * 2048];     // [N=4096, K=2048] fp16 (Q|K|V rows)
__device__ __half g_wo[(size_t)2048 * 2048];       // Wo^T [N,K] fp16
__device__ __half g_ctx[(size_t)MM * HH];          // [b*T+t, h*HD+d] fp16
__device__ float g_cos[TT * 64];
__device__ float g_sin[TT * 64];

// ---------------- helpers ----------------------------------------------------
__device__ __forceinline__ uint32_t smem_u32(const void* p) {
    uint32_t a;
    asm("{ .reg .u64 t; cvta.to.shared.u64 t, %1; cvt.u32.u64 %0, t; }" : "=r"(a) : "l"(p));
    return a;
}

__device__ __forceinline__ void mma_f16(float c[4], const uint32_t a[4],
                                        uint32_t b0, uint32_t b1) {
    asm volatile(
        "mma.sync.aligned.m16n8k16.row.col.f32.f16.f16.f32 "
        "{%0,%1,%2,%3}, {%4,%5,%6,%7}, {%8,%9}, {%0,%1,%2,%3};\n"
        : "+f"(c[0]), "+f"(c[1]), "+f"(c[2]), "+f"(c[3])
        : "r"(a[0]), "r"(a[1]), "r"(a[2]), "r"(a[3]), "r"(b0), "r"(b1));
}

#define LDSM_X4(R0,R1,R2,R3,ADDR)                                              \
    asm volatile("ldmatrix.sync.aligned.m8n8.x4.shared.b16 {%0,%1,%2,%3}, [%4];" \
        : "=r"(R0), "=r"(R1), "=r"(R2), "=r"(R3) : "r"(ADDR))
#define LDSM_X4T(R0,R1,R2,R3,ADDR)                                             \
    asm volatile("ldmatrix.sync.aligned.m8n8.x4.trans.shared.b16 {%0,%1,%2,%3}, [%4];" \
        : "=r"(R0), "=r"(R1), "=r"(R2), "=r"(R3) : "r"(ADDR))

#define CP_ASYNC16(SMEM, GPTR) \
    asm volatile("cp.async.cg.shared.global [%0], [%1], 16;" :: "r"(SMEM), "l"(GPTR) : "memory")
#define CP_COMMIT() asm volatile("cp.async.commit_group;" ::: "memory")
#define CP_WAIT1()  asm volatile("cp.async.wait_group 1;" ::: "memory")

// ---------------- RoPE tables (fp64 angle, fp32 trig after reduction) ---------
__global__ void rope_table_kernel() {
    int t = blockIdx.x * 2 + (threadIdx.x >> 6);
    int j = threadIdx.x & 63;  // 0..63
    double inv = exp(-(double)j * (13.815510557964274 / 64.0)); // theta=1e6
    double ang = (double)t * inv;
    const double TWO_PI = 6.283185307179586476925286766559;
    double red = ang - TWO_PI * floor(ang * (1.0 / TWO_PI));
    float c, s;
    sincosf((float)red, &s, &c);
    g_cos[t * 64 + j] = c;
    g_sin[t * 64 + j] = s;
}

// ---------------- fp32 -> fp16 convert ----------------------------------------
__global__ __launch_bounds__(256) void conv_half_kernel(
    const float* __restrict__ in, __half* __restrict__ out, size_t n)
{
    size_t i = ((size_t)blockIdx.x * 256 + threadIdx.x) * 4;
    if (i < n) {
        float4 v = *(const float4*)(in + i);
        *(__half2*)(out + i)     = __floats2half2_rn(v.x, v.y);
        *(__half2*)(out + i + 2) = __floats2half2_rn(v.z, v.w);
    }
}

// ---------------- W [K,N] fp32 -> Wt [N,K] fp16 -------------------------------
__global__ __launch_bounds__(256) void wt_half_kernel(
    const float* __restrict__ W, __half* __restrict__ Wt, int K, int N_)
{
    __shared__ float t[32][33];
    int n0 = blockIdx.x * 32, k0 = blockIdx.y * 32;
    int tx = threadIdx.x & 31, ty = threadIdx.x >> 5;   // 32 x 8
    #pragma unroll
    for (int i = 0; i < 32; i += 8)
        t[ty + i][tx] = W[(size_t)(k0 + ty + i) * N_ + n0 + tx];
    __syncthreads();
    #pragma unroll
    for (int i = 0; i < 32; i += 8)
        Wt[(size_t)(n0 + ty + i) * K + k0 + tx] = __float2half(t[tx][ty + i]);
}

// ---------------- fp16 tensor-core GEMM: C[M,N] = A[M,K] @ B[N,K]^T -----------
// BK=32, double-buffered smem, ldmatrix fragment loads.
#define GAS 40   // smem row stride in halves (80B = 5x16B, odd -> ldmatrix clean)
#define GSTG (128 * GAS)
__global__ __launch_bounds__(256, 2) void gemm_fp16_kernel(
    const __half* __restrict__ A, const __half* __restrict__ Bm,
    float* __restrict__ C, int M, int N_, int K)
{
    __shared__ __half As[2 * GSTG];
    __shared__ __half Bs[2 * GSTG];

    int tid = threadIdx.x;
    int wid = tid >> 5, lane = tid & 31;
    int g = lane >> 2, tg = lane & 3;
    int lr = lane & 7;
    int lm = (lane >> 3) & 1;
    int lh = lane >> 4;
    int sel = lane >> 3;
    int warpRow = wid >> 1, warpCol = wid & 1;  // 4 x 2 warps
    int brow = blockIdx.y * 128, bcol = blockIdx.x * 128;

    int rowL[2], segL[2];
    #pragma unroll
    for (int it = 0; it < 2; ++it) {
        int idx = it * 256 + tid;
        rowL[it] = idx >> 2;
        segL[it] = (idx & 3) * 8;
    }
    const __half* ApL[2];
    const __half* BpL[2];
    #pragma unroll
    for (int it = 0; it < 2; ++it) {
        ApL[it] = A  + (size_t)(brow + rowL[it]) * K + segL[it];
        BpL[it] = Bm + (size_t)(bcol + rowL[it]) * K + segL[it];
    }

    uint32_t sA = smem_u32(As), sB = smem_u32(Bs);

    float acc[2][8][4];
    #pragma unroll
    for (int mi = 0; mi < 2; mi++)
        #pragma unroll
        for (int ni = 0; ni < 8; ni++)
            #pragma unroll
            for (int c = 0; c < 4; c++) acc[mi][ni][c] = 0.f;

    #pragma unroll
    for (int it = 0; it < 2; ++it) {
        *(int4*)&As[rowL[it] * GAS + segL[it]] = *(const int4*)ApL[it];
        *(int4*)&Bs[rowL[it] * GAS + segL[it]] = *(const int4*)BpL[it];
    }
    __syncthreads();

    int buf = 0;
    for (int k0 = 0; k0 < K; k0 += 32) {
        int4 pa[2], pb[2];
        bool more = (k0 + 32 < K);
        if (more) {
            #pragma unroll
            for (int it = 0; it < 2; ++it) {
                pa[it] = *(const int4*)(ApL[it] + k0 + 32);
                pb[it] = *(const int4*)(BpL[it] + k0 + 32);
            }
        }

        uint32_t bA = sA + buf * (GSTG * 2);
        uint32_t bB = sB + buf * (GSTG * 2);
        #pragma unroll
        for (int ks = 0; ks < 2; ++ks) {
            int kk = ks * 16;
            uint32_t af[2][4];
            #pragma unroll
            for (int mi = 0; mi < 2; mi++) {
                uint32_t addr = bA + (uint32_t)(((warpRow * 32 + mi * 16 + lr + lm * 8) * GAS
                                                 + kk + lh * 8) * 2);
                LDSM_X4(af[mi][0], af[mi][1], af[mi][2], af[mi][3], addr);
            }
            uint32_t bf[8][2];
            #pragma unroll
            for (int nb = 0; nb < 4; nb++) {
                int n0 = warpCol * 64 + nb * 16;
                uint32_t addr = bB + (uint32_t)(((n0 + lr + (sel >> 1) * 8) * GAS
                                                 + kk + (sel & 1) * 8) * 2);
                LDSM_X4(bf[2 * nb][0], bf[2 * nb][1], bf[2 * nb + 1][0], bf[2 * nb + 1][1], addr);
            }
            #pragma unroll
            for (int mi = 0; mi < 2; mi++)
                #pragma unroll
                for (int ni = 0; ni < 8; ni++)
                    mma_f16(acc[mi][ni], af[mi], bf[ni][0], bf[ni][1]);
        }

        if (more) {
            __half* Ad = As + (buf ^ 1) * GSTG;
            __half* Bd = Bs + (buf ^ 1) * GSTG;
            #pragma unroll
            for (int it = 0; it < 2; ++it) {
                *(int4*)&Ad[rowL[it] * GAS + segL[it]] = pa[it];
                *(int4*)&Bd[rowL[it] * GAS + segL[it]] = pb[it];
            }
        }
        __syncthreads();
        buf ^= 1;
    }

    #pragma unroll
    for (int mi = 0; mi < 2; mi++) {
        int r0 = brow + warpRow * 32 + mi * 16 + g;
        #pragma unroll
        for (int ni = 0; ni < 8; ni++) {
            int cn = bcol + warpCol * 64 + ni * 8 + tg * 2;
            *(float2*)(C + (size_t)r0 * N_ + cn) = make_float2(acc[mi][ni][0], acc[mi][ni][1]);
            *(float2*)(C + (size_t)(r0 + 8) * N_ + cn) = make_float2(acc[mi][ni][2], acc[mi][ni][3]);
        }
    }
}

// ------------- RMSNorm + RoPE + transpose -> [b,h,t,d] fp16 -------------------
__global__ __launch_bounds__(128) void norm_rope_kernel(
    const float* __restrict__ src, __half* __restrict__ dst,
    const float* __restrict__ w, int nheads, int srcStride)
{
    int r = blockIdx.x;              // (b*T+t)*nheads + h
    int d = threadIdx.x;             // 0..127
    int h  = r % nheads;
    int bt = r / nheads;
    int t  = bt % TT;
    int b  = bt / TT;

    float val = src[(size_t)bt * srcStride + h * HD + d];
    __shared__ float red[4];
    __shared__ float sh[HD];

    float ss = val * val;
    #pragma unroll
    for (int off = 16; off; off >>= 1)
        ss += __shfl_xor_sync(0xffffffffu, ss, off);
    if ((d & 31) == 0) red[d >> 5] = ss;
    __syncthreads();
    float tot = red[0] + red[1] + red[2] + red[3];
    float nv = val * rsqrtf(tot * (1.0f / HD) + 1e-6f) * w[d];
    sh[d] = nv;
    __syncthreads();

    int j = d & 63;
    float c = g_cos[t * 64 + j];
    float s = g_sin[t * 64 + j];
    float other = (d < 64) ? -sh[d + 64] : sh[d - 64];
    float out = nv * c + other * s;

    dst[((size_t)(b * nheads + h) * TT + t) * HD + d] = __float2half(out);
}

// ------------- V transpose -> [b,h,t,d] fp16 ----------------------------------
__global__ __launch_bounds__(128) void transpose_kernel(
    const float* __restrict__ src, __half* __restrict__ dst, int nheads, int srcStride)
{
    int r = blockIdx.x;
    int d = threadIdx.x;
    int h  = r % nheads;
    int bt = r / nheads;
    int t  = bt % TT;
    int b  = bt / TT;
    dst[((size_t)(b * nheads + h) * TT + t) * HD + d] =
        __float2half(src[(size_t)bt * srcStride + h * HD + d]);
}

// ------------- Causal flash attention: fp16 mma, cp.async K/V pipeline --------
#define US_STR 136   // halves; 272B rows -> ldmatrix conflict-free
#define PS_STR 72
#define FL_KV  (64 * US_STR)
#define FL_U   (128 * US_STR)
#define FLASH_SMEM ((2 * FL_KV + FL_U) * 2)

__global__ __launch_bounds__(256) void flash_fp16_kernel(
    const __half* __restrict__ Q, const __half* __restrict__ Kt,
    const __half* __restrict__ Vt, __half* __restrict__ ctx)
{
    extern __shared__ __half smh[];
    __half* Ks = smh;
    __half* Vs = smh + FL_KV;
    __half* Us = smh + 2 * FL_KV;
    __half* Ps = Us;

    int tid = threadIdx.x;
    int wid = tid >> 5, lane = tid & 31;
    int g = lane >> 2, tg = lane & 3;
    int lr = lane & 7;
    int lm = (lane >> 3) & 1;
    int lh = lane >> 4;
    int p8 = (lane >> 3) & 1;
    int p16 = lane >> 4;

    int hw = wid >> 2;
    int w4 = wid & 3;
    int base = w4 * 16;

    int qb = blockIdx.x;
    int bk = blockIdx.y;
    int b = bk / NKV, kvh = bk % NKV;
    int h = kvh * 2 + hw;

    const __half* Kbase = Kt + ((size_t)(b * NKV + kvh) * TT) * HD;
    const __half* Vbase = Vt + ((size_t)(b * NKV + kvh) * TT) * HD;

    uint32_t sK = smem_u32(Ks), sV = smem_u32(Vs), sU = smem_u32(Us), sP = sU;

    // cp.async mapping: tile = 64 rows x 128 halves; 1024x16B; 4 per thread
    int cprow[4], cpc8[4];
    uint32_t cpK[4], cpV[4];
    #pragma unroll
    for (int it = 0; it < 4; ++it) {
        int idx = it * 256 + tid;
        cprow[it] = idx >> 4;
        cpc8[it]  = (idx & 15) * 8;
        cpK[it] = sK + (uint32_t)((cprow[it] * US_STR + cpc8[it]) * 2);
        cpV[it] = sV + (uint32_t)((cprow[it] * US_STR + cpc8[it]) * 2);
    }

    // prefetch K0, V0 (overlaps Q staging)
    #pragma unroll
    for (int it = 0; it < 4; ++it)
        CP_ASYNC16(cpK[it], Kbase + (size_t)cprow[it] * HD + cpc8[it]);
    CP_COMMIT();
    #pragma unroll
    for (int it = 0; it < 4; ++it)
        CP_ASYNC16(cpV[it], Vbase + (size_t)cprow[it] * HD + cpc8[it]);
    CP_COMMIT();

    // stage Q, load fragments
    {
        const __half* Qh = Q + ((size_t)(b * NH + kvh * 2 + hw) * TT + qb * 64) * HD;
        int t128 = tid & 127;
        #pragma unroll
        for (int it = 0; it < 8; ++it) {
            int idx = it * 128 + t128;
            int r = idx >> 4;
            int c8 = (idx & 15) * 8;
            *(int4*)&Us[(hw * 64 + r) * US_STR + c8] =
                *(const int4*)(Qh + (size_t)r * HD + c8);
        }
    }
    __syncthreads();

    uint32_t qa[8][4];
    #pragma unroll
    for (int ks = 0; ks < 8; ++ks) {
        uint32_t au = sU + (uint32_t)(((hw * 64 + base + lr + lm * 8) * US_STR + ks * 16 + lh * 8) * 2);
        LDSM_X4(qa[ks][0], qa[ks][1], qa[ks][2], qa[ks][3], au);
    }

    float o[16][4];
    #pragma unroll
    for (int ni = 0; ni < 16; ni++)
        #pragma unroll
        for (int c = 0; c < 4; c++) o[ni][c] = 0.f;
    float mrow[2] = {-1e30f, -1e30f};
    float lrow[2] = {0.f, 0.f};

    const float scale = 0.08838834764831845f;   // 128^-0.5
    const float L2E = 1.44269504088896f;

    for (int kb = 0; kb <= qb; ++kb) {
        bool more = (kb < qb);
        // K(kb) ready (V(kb) may still be in flight)
        CP_WAIT1();
        __syncthreads();

        // ---- S = Q @ K^T (x4 pair loads) ------------------------------------
        float s[8][4];
        #pragma unroll
        for (int ni = 0; ni < 8; ni++)
            #pragma unroll
            for (int c = 0; c < 4; c++) s[ni][c] = 0.f;

        #pragma unroll
        for (int ks = 0; ks < 8; ++ks) {
            int kk = ks * 16;
            #pragma unroll
            for (int np = 0; np < 4; np++) {
                uint32_t r0, r1, r2, r3;
                uint32_t ak = sK + (uint32_t)(((np * 16 + p16 * 8 + lr) * US_STR
                                               + kk + p8 * 8) * 2);
                LDSM_X4(r0, r1, r2, r3, ak);
                mma_f16(s[2 * np],     qa[ks], r0, r1);
                mma_f16(s[2 * np + 1], qa[ks], r2, r3);
            }
        }
        __syncthreads();   // all warps done reading Ks

        // prefetch K(kb+1) — overlaps softmax + PV
        if (more) {
            const __half* Kn = Kbase + (size_t)(kb + 1) * 64 * HD;
            #pragma unroll
            for (int it = 0; it < 4; ++it)
                CP_ASYNC16(cpK[it], Kn + (size_t)cprow[it] * HD + cpc8[it]);
        }
        CP_COMMIT();

        // ---- online softmax --------------------------------------------------
        bool diag = (kb == qb);
        int rowA = base + g;
        int rowB = rowA + 8;
        float mA = -1e30f, mB = -1e30f;
        #pragma unroll
        for (int ni = 0; ni < 8; ni++) {
            #pragma unroll
            for (int c = 0; c < 4; c++) {
                float sv = s[ni][c] * scale;
                if (diag) {
                    int kcol = ni * 8 + tg * 2 + (c & 1);
                    int qrow = (c < 2) ? rowA : rowB;
                    if (kcol > qrow) sv = -1e30f;
                }
                s[ni][c] = sv;
            }
            mA = fmaxf(mA, fmaxf(s[ni][0], s[ni][1]));
            mB = fmaxf(mB, fmaxf(s[ni][2], s[ni][3]));
        }
        #pragma unroll
        for (int off = 1; off < 4; off <<= 1) {
            mA = fmaxf(mA, __shfl_xor_sync(0xffffffffu, mA, off));
            mB = fmaxf(mB, __shfl_xor_sync(0xffffffffu, mB, off));
        }
        float mnA = fmaxf(mrow[0], mA);
        float mnB = fmaxf(mrow[1], mB);
        float alA = exp2f((mrow[0] - mnA) * L2E);
        float alB = exp2f((mrow[1] - mnB) * L2E);
        mrow[0] = mnA; mrow[1] = mnB;

        float lA = 0.f, lB = 0.f;
        #pragma unroll
        for (int ni = 0; ni < 8; ni++) {
            s[ni][0] = exp2f((s[ni][0] - mnA) * L2E);
            s[ni][1] = exp2f((s[ni][1] - mnA) * L2E);
            s[ni][2] = exp2f((s[ni][2] - mnB) * L2E);
            s[ni][3] = exp2f((s[ni][3] - mnB) * L2E);
            lA += s[ni][0] + s[ni][1];
            lB += s[ni][2] + s[ni][3];
        }
        #pragma unroll
        for (int off = 1; off < 4; off <<= 1) {
            lA += __shfl_xor_sync(0xffffffffu, lA, off);
            lB += __shfl_xor_sync(0xffffffffu, lB, off);
        }
        lrow[0] = lrow[0] * alA + lA;
        lrow[1] = lrow[1] * alB + lB;
        #pragma unroll
        for (int ni = 0; ni < 16; ni++) {
            o[ni][0] *= alA; o[ni][1] *= alA;
            o[ni][2] *= alB; o[ni][3] *= alB;
        }

        int prowA = hw * 64 + rowA;
        int prowB = hw * 64 + rowB;
        #pragma unroll
        for (int ni = 0; ni < 8; ni++) {
            int cn = ni * 8 + tg * 2;
            *(__half2*)&Ps[prowA * PS_STR + cn] = __floats2half2_rn(s[ni][0], s[ni][1]);
            *(__half2*)&Ps[prowB * PS_STR + cn] = __floats2half2_rn(s[ni][2], s[ni][3]);
        }
        __syncwarp();

        // V(kb) ready (K(kb+1) may still be in flight)
        CP_WAIT1();
        __syncthreads();

        // ---- O += P @ V (x4.trans pair loads) --------------------------------
        #pragma unroll
        for (int ks = 0; ks < 4; ++ks) {
            int kk = ks * 16;
            uint32_t pa4[4];
            uint32_t ap = sP + (uint32_t)(((hw * 64 + base + lr + lm * 8) * PS_STR + kk + lh * 8) * 2);
            LDSM_X4(pa4[0], pa4[1], pa4[2], pa4[3], ap);
            #pragma unroll
            for (int np = 0; np < 8; np++) {
                uint32_t r0, r1, r2, r3;
                uint32_t av = sV + (uint32_t)(((kk + p8 * 8 + lr) * US_STR
                                               + np * 16 + p16 * 8) * 2);
                LDSM_X4T(r0, r1, r2, r3, av);
                mma_f16(o[2 * np],     pa4, r0, r1);
                mma_f16(o[2 * np + 1], pa4, r2, r3);
            }
        }
        __syncthreads();   // all warps done reading Vs

        // prefetch V(kb+1) — overlaps next S-phase
        if (more) {
            const __half* Vn = Vbase + (size_t)(kb + 1) * 64 * HD;
            #pragma unroll
            for (int it = 0; it < 4; ++it)
                CP_ASYNC16(cpV[it], Vn + (size_t)cprow[it] * HD + cpc8[it]);
        }
        CP_COMMIT();
    }

    float ivA = 1.0f / lrow[0];
    float ivB = 1.0f / lrow[1];
    int qA = qb * 64 + base + g;
    int qB = qA + 8;
    size_t offA = (size_t)(b * TT + qA) * (NH * HD) + h * HD;
    size_t offB = (size_t)(b * TT + qB) * (NH * HD) + h * HD;
    #pragma unroll
    for (int ni = 0; ni < 16; ni++) {
        int dn = ni * 8 + tg * 2;
        *(__half2*)(ctx + offA + dn) = __floats2half2_rn(o[ni][0] * ivA, o[ni][1] * ivA);
        *(__half2*)(ctx + offB + dn) = __floats2half2_rn(o[ni][2] * ivB, o[ni][3] * ivB);
    }
}

// ---------------------------- launch -----------------------------------------
extern "C" void kernel_launch(void* const* d_in, const int* in_sizes, int n_in,
                              void* d_out, int out_size)
{
    const float* x    = (const float*)d_in[0];
    // d_in[1] = attn_mask (pure causal; applied analytically)
    const float* Wq   = (const float*)d_in[2];
    const float* Wk   = (const float*)d_in[3];
    const float* Wv   = (const float*)d_in[4];
    const float* Wo   = (const float*)d_in[5];
    const float* qnw  = (const float*)d_in[6];
    const float* knw  = (const float*)d_in[7];
    float* out = (float*)d_out;

    float *qkvraw;
    __half *qt, *kt, *vt, *xh, *wqkv, *wo, *ctx;
    cudaGetSymbolAddress((void**)&qkvraw, g_qkvraw);
    cudaGetSymbolAddress((void**)&qt,   g_qt);
    cudaGetSymbolAddress((void**)&kt,   g_kt);
    cudaGetSymbolAddress((void**)&vt,   g_vt);
    cudaGetSymbolAddress((void**)&xh,   g_xh);
    cudaGetSymbolAddress((void**)&wqkv, g_wqkv);
    cudaGetSymbolAddress((void**)&wo,   g_wo);
    cudaGetSymbolAddress((void**)&ctx,  g_ctx);

    cudaFuncSetAttribute(flash_fp16_kernel, cudaFuncAttributeMaxDynamicSharedMemorySize,
                         FLASH_SMEM);

    // 0: rope table
    rope_table_kernel<<<TT / 2, 128>>>();
    // 1: x -> fp16
    conv_half_kernel<<<(unsigned)(((size_t)MM * HH / 4 + 255) / 256), 256>>>(
        x, xh, (size_t)MM * HH);
    // 2-4: W^T fp16 (QKV into one buffer)
    wt_half_kernel<<<dim3(2048 / 32, 2048 / 32), 256>>>(Wq, wqkv, 2048, 2048);
    wt_half_kernel<<<dim3(1024 / 32, 2048 / 32), 256>>>(Wk, wqkv + (size_t)2048 * 2048, 2048, 1024);
    wt_half_kernel<<<dim3(1024 / 32, 2048 / 32), 256>>>(Wv, wqkv + (size_t)3072 * 2048, 2048, 1024);
    // 5: fused QKV projection (N=4096)  [ncu capture slot]
    gemm_fp16_kernel<<<dim3(4096 / 128, MM / 128), 256>>>(xh, wqkv, qkvraw, MM, 4096, HH);
    // 6-8: RMSNorm/RoPE/transpose -> fp16
    norm_rope_kernel<<<BB * TT * NH, 128>>>(qkvraw, qt, qnw, NH, 4096);
    norm_rope_kernel<<<BB * TT * NKV, 128>>>(qkvraw + 2048, kt, knw, NKV, 4096);
    transpose_kernel<<<BB * TT * NKV, 128>>>(qkvraw + 3072, vt, NKV, 4096);
    // 9: Wo^T fp16
    wt_half_kernel<<<dim3(2048 / 32, 2048 / 32), 256>>>(Wo, wo, 2048, 2048);
    // 10: flash attention (fp16 mma, 2 GQA heads/CTA, cp.async pipeline)
    flash_fp16_kernel<<<dim3(TT / 64, BB * NKV), 256, FLASH_SMEM>>>(qt, kt, vt, ctx);
    // 11: output projection
    gemm_fp16_kernel<<<dim3(2048 / 128, MM / 128), 256>>>(ctx, wo, out, MM, 2048, HH);
}